// round 1
// baseline (speedup 1.0000x reference)
#include <cuda_runtime.h>

#define MOLS 128
#define L 256
#define H 768
#define NH 12
#define HD 64
#define NROWS (MOLS * L)

// ---------------- scratch (device globals: no allocation allowed) ----------
__device__ float g_X[(size_t)NROWS * H];   // masked input x
__device__ float g_Q[(size_t)NROWS * H];   // Q, later reused as OUT (post-proj)
__device__ float g_K[(size_t)NROWS * H];
__device__ float g_V[(size_t)NROWS * H];
__device__ float g_C[(size_t)NROWS * H];   // attention context

// ---------------- masked gather: x = atom[idx] * mask ----------------------
__global__ void build_x_kernel(const float* __restrict__ atom,
                               const int* __restrict__ a_starts,
                               const int* __restrict__ a_sizes) {
    int i = blockIdx.x * blockDim.x + threadIdx.x;     // float4 index
    const int W4 = H / 4;
    int row = i / W4;
    int c4  = (i - row * W4) * 4;
    int m = row / L;
    int l = row - m * L;
    float4 val = make_float4(0.f, 0.f, 0.f, 0.f);
    if (l < a_sizes[m]) {
        int src = a_starts[m] + l;
        val = *(const float4*)&atom[(size_t)src * H + c4];
    }
    *(float4*)&g_X[(size_t)row * H + c4] = val;
}

// ---------------- C[n,o] = sum_h A[n,h]*B[o,h] + bias[o] -------------------
// 128x128 tile, BK=8, 256 threads, 8x8 micro-tile per thread.
__global__ __launch_bounds__(256) void gemm_bt_kernel(
    const float* __restrict__ A, const float* __restrict__ B,
    const float* __restrict__ bias, float* __restrict__ C) {
    __shared__ float As[8][128];
    __shared__ float Bs[8][128];
    const int bm = blockIdx.y * 128;
    const int bn = blockIdx.x * 128;
    const int tid = threadIdx.x;
    const int tx = (tid & 15) * 8;
    const int ty = (tid >> 4) * 8;
    const int lrow = tid >> 1;
    const int lcol = (tid & 1) * 4;

    float acc[8][8];
#pragma unroll
    for (int i = 0; i < 8; i++)
#pragma unroll
        for (int j = 0; j < 8; j++) acc[i][j] = 0.f;

    const float* Aptr = A + (size_t)(bm + lrow) * H + lcol;
    const float* Bptr = B + (size_t)(bn + lrow) * H + lcol;

    for (int k0 = 0; k0 < H; k0 += 8) {
        float4 a4 = *(const float4*)(Aptr + k0);
        float4 b4 = *(const float4*)(Bptr + k0);
        As[lcol + 0][lrow] = a4.x; As[lcol + 1][lrow] = a4.y;
        As[lcol + 2][lrow] = a4.z; As[lcol + 3][lrow] = a4.w;
        Bs[lcol + 0][lrow] = b4.x; Bs[lcol + 1][lrow] = b4.y;
        Bs[lcol + 2][lrow] = b4.z; Bs[lcol + 3][lrow] = b4.w;
        __syncthreads();
#pragma unroll
        for (int kk = 0; kk < 8; kk++) {
            float ar[8], br[8];
#pragma unroll
            for (int i = 0; i < 8; i++) ar[i] = As[kk][ty + i];
#pragma unroll
            for (int j = 0; j < 8; j++) br[j] = Bs[kk][tx + j];
#pragma unroll
            for (int i = 0; i < 8; i++)
#pragma unroll
                for (int j = 0; j < 8; j++) acc[i][j] = fmaf(ar[i], br[j], acc[i][j]);
        }
        __syncthreads();
    }
#pragma unroll
    for (int i = 0; i < 8; i++) {
        float* Crow = C + (size_t)(bm + ty + i) * H + bn + tx;
#pragma unroll
        for (int j = 0; j < 8; j++) Crow[j] = acc[i][j] + bias[bn + tx + j];
    }
}

// ---------------- attention: one CTA per (head, molecule) ------------------
// K,V staged in 128KB dynamic smem; one query row per thread.
// Pass 1: row max (no exp). Pass 2: exp + sum + weighted-V accumulate.
// Skipping k >= size is exactly the -1e9 mask (expf underflows to 0).
__global__ __launch_bounds__(256, 1) void attn_kernel(const int* __restrict__ a_sizes) {
    extern __shared__ float sm[];
    float* Ks = sm;
    float* Vs = sm + L * HD;
    const int h = blockIdx.x, m = blockIdx.y;
    const int tid = threadIdx.x;
    const int size = a_sizes[m];

    for (int i = tid; i < L * HD / 4; i += 256) {
        int r = i >> 4;              // HD/4 == 16
        int c = (i & 15) << 2;
        size_t src = (size_t)(m * L + r) * H + h * HD + c;
        *(float4*)&Ks[r * HD + c] = *(const float4*)&g_K[src];
        *(float4*)&Vs[r * HD + c] = *(const float4*)&g_V[src];
    }
    __syncthreads();

    const int q = tid;
    float qr[HD];
    {
        const float* Qrow = &g_Q[(size_t)(m * L + q) * H + h * HD];
#pragma unroll
        for (int d = 0; d < HD; d += 4) {
            float4 t = *(const float4*)&Qrow[d];
            qr[d] = t.x; qr[d + 1] = t.y; qr[d + 2] = t.z; qr[d + 3] = t.w;
        }
    }
    const float scale = 0.125f;   // HD^-0.5

    float mx = -1e30f;
    for (int k = 0; k < size; k++) {
        const float* kr = &Ks[k * HD];
        float s = 0.f;
#pragma unroll
        for (int d = 0; d < HD; d++) s = fmaf(qr[d], kr[d], s);
        mx = fmaxf(mx, s * scale);
    }

    float acc[HD];
#pragma unroll
    for (int d = 0; d < HD; d++) acc[d] = 0.f;
    float sum = 0.f;
    for (int k = 0; k < size; k++) {
        const float* kr = &Ks[k * HD];
        float s = 0.f;
#pragma unroll
        for (int d = 0; d < HD; d++) s = fmaf(qr[d], kr[d], s);
        float p = __expf(s * scale - mx);
        sum += p;
        const float* vr = &Vs[k * HD];
#pragma unroll
        for (int d = 0; d < HD; d++) acc[d] = fmaf(p, vr[d], acc[d]);
    }
    float inv = 1.f / sum;
    float* Crow = &g_C[(size_t)(m * L + q) * H + h * HD];
#pragma unroll
    for (int d = 0; d < HD; d += 4) {
        float4 t = make_float4(acc[d] * inv, acc[d + 1] * inv,
                               acc[d + 2] * inv, acc[d + 3] * inv);
        *(float4*)&Crow[d] = t;
    }
}

// -------- residual + LayerNorm + gamma/beta + mask + scatter ---------------
__global__ __launch_bounds__(256) void ln_kernel(
    const float* __restrict__ gamma, const float* __restrict__ beta,
    const int* __restrict__ a_starts, const int* __restrict__ a_sizes,
    float* __restrict__ out) {
    const int row = blockIdx.x;
    const int m = row / L;
    const int l = row - m * L;
    const int tid = threadIdx.x;   // 256 threads, 3 columns each

    __shared__ float redbuf[8];
    __shared__ float stat[2];

    float y[3];
    float s = 0.f;
#pragma unroll
    for (int i = 0; i < 3; i++) {
        int col = tid + i * 256;
        float v = g_Q[(size_t)row * H + col] + g_X[(size_t)row * H + col];
        y[i] = v;
        s += v;
    }
#pragma unroll
    for (int o = 16; o > 0; o >>= 1) s += __shfl_xor_sync(0xffffffffu, s, o);
    if ((tid & 31) == 0) redbuf[tid >> 5] = s;
    __syncthreads();
    if (tid == 0) {
        float t = 0.f;
#pragma unroll
        for (int i = 0; i < 8; i++) t += redbuf[i];
        stat[0] = t;
    }
    __syncthreads();
    const float mu = stat[0] * (1.f / 768.f);

    float vs = 0.f;
#pragma unroll
    for (int i = 0; i < 3; i++) {
        float d = y[i] - mu;
        vs += d * d;
    }
#pragma unroll
    for (int o = 16; o > 0; o >>= 1) vs += __shfl_xor_sync(0xffffffffu, vs, o);
    if ((tid & 31) == 0) redbuf[tid >> 5] = vs;
    __syncthreads();
    if (tid == 0) {
        float t = 0.f;
#pragma unroll
        for (int i = 0; i < 8; i++) t += redbuf[i];
        stat[1] = t;
    }
    __syncthreads();
    const float rstd = rsqrtf(stat[1] * (1.f / 768.f) + 1e-5f);

    const bool valid = l < a_sizes[m];
    const int dst = a_starts[m] + l;
#pragma unroll
    for (int i = 0; i < 3; i++) {
        int col = tid + i * 256;
        float o = valid ? ((y[i] - mu) * rstd * gamma[col] + beta[col]) : 0.f;
        out[(size_t)dst * H + col] = o;
    }
}

// ---------------------------------------------------------------------------
extern "C" void kernel_launch(void* const* d_in, const int* in_sizes, int n_in,
                              void* d_out, int out_size) {
    const float* atom     = (const float*)d_in[0];
    const float* Wq       = (const float*)d_in[1];
    const float* bq       = (const float*)d_in[2];
    const float* Wk       = (const float*)d_in[3];
    const float* bk       = (const float*)d_in[4];
    const float* Wv       = (const float*)d_in[5];
    const float* bv       = (const float*)d_in[6];
    const float* Wo       = (const float*)d_in[7];
    const float* bo       = (const float*)d_in[8];
    const float* gamma    = (const float*)d_in[9];
    const float* beta     = (const float*)d_in[10];
    const int*   a_starts = (const int*)d_in[11];
    const int*   a_sizes  = (const int*)d_in[12];
    float* out = (float*)d_out;

    float *pX, *pQ, *pK, *pV, *pC;
    cudaGetSymbolAddress((void**)&pX, g_X);
    cudaGetSymbolAddress((void**)&pQ, g_Q);
    cudaGetSymbolAddress((void**)&pK, g_K);
    cudaGetSymbolAddress((void**)&pV, g_V);
    cudaGetSymbolAddress((void**)&pC, g_C);

    const int attn_smem = 2 * L * HD * (int)sizeof(float);   // 128 KB
    cudaFuncSetAttribute(attn_kernel, cudaFuncAttributeMaxDynamicSharedMemorySize,
                         attn_smem);

    // scatter semantics: rows not targeted stay zero
    cudaMemsetAsync(d_out, 0, (size_t)out_size * sizeof(float), 0);

    build_x_kernel<<<(NROWS * H / 4) / 256, 256>>>(atom, a_starts, a_sizes);

    dim3 ggrid(H / 128, NROWS / 128);
    gemm_bt_kernel<<<ggrid, 256>>>(pX, Wq, bq, pQ);
    gemm_bt_kernel<<<ggrid, 256>>>(pX, Wk, bk, pK);
    gemm_bt_kernel<<<ggrid, 256>>>(pX, Wv, bv, pV);

    attn_kernel<<<dim3(NH, MOLS), 256, attn_smem>>>(a_sizes);

    gemm_bt_kernel<<<ggrid, 256>>>(pC, Wo, bo, pQ);   // OUT reuses g_Q

    ln_kernel<<<NROWS, 256>>>(gamma, beta, a_starts, a_sizes, out);
}

// round 2
// speedup vs baseline: 1.0260x; 1.0260x over previous
#include <cuda_runtime.h>
#include <cstdint>

#define MOLS 128
#define L 256
#define H 768
#define NH 12
#define HD 64
#define NROWS (MOLS * L)

// ---------------- scratch (device globals: no allocation allowed) ----------
__device__ float g_X[(size_t)NROWS * H];   // masked input x
__device__ float g_Q[(size_t)NROWS * H];   // Q, later reused as OUT (post-proj)
__device__ float g_K[(size_t)NROWS * H];
__device__ float g_V[(size_t)NROWS * H];
__device__ float g_C[(size_t)NROWS * H];   // attention context

// ---------------- masked gather: x = atom[idx] * mask ----------------------
__global__ void build_x_kernel(const float* __restrict__ atom,
                               const int* __restrict__ a_starts,
                               const int* __restrict__ a_sizes) {
    int i = blockIdx.x * blockDim.x + threadIdx.x;     // float4 index
    const int W4 = H / 4;
    int row = i / W4;
    int c4  = (i - row * W4) * 4;
    int m = row / L;
    int l = row - m * L;
    float4 val = make_float4(0.f, 0.f, 0.f, 0.f);
    if (l < a_sizes[m]) {
        int src = a_starts[m] + l;
        val = *(const float4*)&atom[(size_t)src * H + c4];
    }
    *(float4*)&g_X[(size_t)row * H + c4] = val;
}

// ---------------- tf32 helpers ---------------------------------------------
__device__ __forceinline__ uint32_t f2tf32(float x) {
    uint32_t r;
    asm("cvt.rna.tf32.f32 %0, %1;" : "=r"(r) : "f"(x));
    return r;
}

__device__ __forceinline__ void mma_tf32(float d[4],
                                         uint32_t a0, uint32_t a1,
                                         uint32_t a2, uint32_t a3,
                                         uint32_t b0, uint32_t b1) {
    asm volatile(
        "mma.sync.aligned.m16n8k8.row.col.f32.tf32.tf32.f32 "
        "{%0,%1,%2,%3}, {%4,%5,%6,%7}, {%8,%9}, {%0,%1,%2,%3};\n"
        : "+f"(d[0]), "+f"(d[1]), "+f"(d[2]), "+f"(d[3])
        : "r"(a0), "r"(a1), "r"(a2), "r"(a3), "r"(b0), "r"(b1));
}

// ---------------- C[n,o] = sum_h A[n,h]*B[o,h] + bias[o] -------------------
// Tensor-core tf32 GEMM with 3-term fp32 compensation (Ahi*Bhi + Ahi*Blo + Alo*Bhi).
// CTA tile 128x128, BK=32, 8 warps (2x4), warp tile 64x32, mma m16n8k8.
#define SA 129   // smem row stride (BM+1): conflict-free transposed STS + frag LDS

__global__ __launch_bounds__(256) void gemm_tf32_kernel(
    const float* __restrict__ A, const float* __restrict__ B,
    const float* __restrict__ bias, float* __restrict__ C) {
    extern __shared__ float smf[];
    float* As_hi = smf;
    float* As_lo = As_hi + 32 * SA;
    float* Bs_hi = As_lo + 32 * SA;
    float* Bs_lo = Bs_hi + 32 * SA;

    const int bm = blockIdx.y * 128;
    const int bn = blockIdx.x * 128;
    const int tid = threadIdx.x;
    const int lane = tid & 31;
    const int wid = tid >> 5;
    const int wm = wid >> 2;            // 0..1 (64-row slab)
    const int wn = wid & 3;             // 0..3 (32-col slab)
    const int lrow = tid >> 1;          // 0..127  (tile row this thread stages)
    const int kb = (tid & 1) * 16;      // k-offset 0 or 16

    float acc[4][4][4];
#pragma unroll
    for (int i = 0; i < 4; i++)
#pragma unroll
        for (int j = 0; j < 4; j++)
#pragma unroll
            for (int t = 0; t < 4; t++) acc[i][j][t] = 0.f;

    const float* Aptr = A + (size_t)(bm + lrow) * H + kb;
    const float* Bptr = B + (size_t)(bn + lrow) * H + kb;

    for (int k0 = 0; k0 < H; k0 += 32) {
        __syncthreads();
#pragma unroll
        for (int j = 0; j < 16; j += 4) {
            float4 a4 = *(const float4*)(Aptr + k0 + j);
            float4 b4 = *(const float4*)(Bptr + k0 + j);
            float av[4] = {a4.x, a4.y, a4.z, a4.w};
            float bv[4] = {b4.x, b4.y, b4.z, b4.w};
#pragma unroll
            for (int t = 0; t < 4; t++) {
                int kr = kb + j + t;
                float ah = __uint_as_float(f2tf32(av[t]));
                As_hi[kr * SA + lrow] = ah;
                As_lo[kr * SA + lrow] = __uint_as_float(f2tf32(av[t] - ah));
                float bh = __uint_as_float(f2tf32(bv[t]));
                Bs_hi[kr * SA + lrow] = bh;
                Bs_lo[kr * SA + lrow] = __uint_as_float(f2tf32(bv[t] - bh));
            }
        }
        __syncthreads();
#pragma unroll
        for (int kk = 0; kk < 32; kk += 8) {
            const int c0 = kk + (lane & 3);
            const int c1 = c0 + 4;
            uint32_t ah[4][4], al[4][4];
#pragma unroll
            for (int mt = 0; mt < 4; mt++) {
                int r0 = wm * 64 + mt * 16 + (lane >> 2);
                ah[mt][0] = __float_as_uint(As_hi[c0 * SA + r0]);
                ah[mt][1] = __float_as_uint(As_hi[c0 * SA + r0 + 8]);
                ah[mt][2] = __float_as_uint(As_hi[c1 * SA + r0]);
                ah[mt][3] = __float_as_uint(As_hi[c1 * SA + r0 + 8]);
                al[mt][0] = __float_as_uint(As_lo[c0 * SA + r0]);
                al[mt][1] = __float_as_uint(As_lo[c0 * SA + r0 + 8]);
                al[mt][2] = __float_as_uint(As_lo[c1 * SA + r0]);
                al[mt][3] = __float_as_uint(As_lo[c1 * SA + r0 + 8]);
            }
#pragma unroll
            for (int nt = 0; nt < 4; nt++) {
                int cn = wn * 32 + nt * 8 + (lane >> 2);
                uint32_t bh0 = __float_as_uint(Bs_hi[c0 * SA + cn]);
                uint32_t bh1 = __float_as_uint(Bs_hi[c1 * SA + cn]);
                uint32_t bl0 = __float_as_uint(Bs_lo[c0 * SA + cn]);
                uint32_t bl1 = __float_as_uint(Bs_lo[c1 * SA + cn]);
#pragma unroll
                for (int mt = 0; mt < 4; mt++) {
                    mma_tf32(acc[mt][nt], ah[mt][0], ah[mt][1], ah[mt][2], ah[mt][3], bh0, bh1);
                    mma_tf32(acc[mt][nt], ah[mt][0], ah[mt][1], ah[mt][2], ah[mt][3], bl0, bl1);
                    mma_tf32(acc[mt][nt], al[mt][0], al[mt][1], al[mt][2], al[mt][3], bh0, bh1);
                }
            }
        }
    }

#pragma unroll
    for (int mt = 0; mt < 4; mt++) {
        int row = bm + wm * 64 + mt * 16 + (lane >> 2);
#pragma unroll
        for (int nt = 0; nt < 4; nt++) {
            int col = bn + wn * 32 + nt * 8 + (lane & 3) * 2;
            float2 bb = *(const float2*)&bias[col];
            float2 v0 = make_float2(acc[mt][nt][0] + bb.x, acc[mt][nt][1] + bb.y);
            float2 v1 = make_float2(acc[mt][nt][2] + bb.x, acc[mt][nt][3] + bb.y);
            *(float2*)&C[(size_t)row * H + col] = v0;
            *(float2*)&C[(size_t)(row + 8) * H + col] = v1;
        }
    }
}

// ---------------- attention: one CTA per (head, molecule) ------------------
// K,V staged in 128KB dynamic smem; one query row per thread.
// Single pass with online softmax (rescale on new running max). Skipping
// k >= size is exactly the -1e9 mask (exp underflows to 0).
__global__ __launch_bounds__(256, 1) void attn_kernel(const int* __restrict__ a_sizes) {
    extern __shared__ float sm[];
    float* Ks = sm;
    float* Vs = sm + L * HD;
    const int h = blockIdx.x, m = blockIdx.y;
    const int tid = threadIdx.x;
    const int size = a_sizes[m];

    for (int i = tid; i < L * HD / 4; i += 256) {
        int r = i >> 4;              // HD/4 == 16
        int c = (i & 15) << 2;
        size_t src = (size_t)(m * L + r) * H + h * HD + c;
        *(float4*)&Ks[r * HD + c] = *(const float4*)&g_K[src];
        *(float4*)&Vs[r * HD + c] = *(const float4*)&g_V[src];
    }
    __syncthreads();

    const int q = tid;
    float qr[HD];
    {
        const float* Qrow = &g_Q[(size_t)(m * L + q) * H + h * HD];
#pragma unroll
        for (int d = 0; d < HD; d += 4) {
            float4 t = *(const float4*)&Qrow[d];
            qr[d] = t.x; qr[d + 1] = t.y; qr[d + 2] = t.z; qr[d + 3] = t.w;
        }
    }
    const float scale = 0.125f;   // HD^-0.5

    float acc[HD];
#pragma unroll
    for (int d = 0; d < HD; d++) acc[d] = 0.f;
    float mx = -1e30f;
    float sum = 0.f;

    for (int k = 0; k < size; k++) {
        const float* kr = &Ks[k * HD];
        float s = 0.f;
#pragma unroll
        for (int d = 0; d < HD; d++) s = fmaf(qr[d], kr[d], s);
        s *= scale;
        if (s > mx) {
            float f = __expf(mx - s);   // first hit: exp(-huge) = 0
            sum *= f;
#pragma unroll
            for (int d = 0; d < HD; d++) acc[d] *= f;
            mx = s;
        }
        float p = __expf(s - mx);
        sum += p;
        const float* vr = &Vs[k * HD];
#pragma unroll
        for (int d = 0; d < HD; d++) acc[d] = fmaf(p, vr[d], acc[d]);
    }
    float inv = 1.f / sum;
    float* Crow = &g_C[(size_t)(m * L + q) * H + h * HD];
#pragma unroll
    for (int d = 0; d < HD; d += 4) {
        float4 t = make_float4(acc[d] * inv, acc[d + 1] * inv,
                               acc[d + 2] * inv, acc[d + 3] * inv);
        *(float4*)&Crow[d] = t;
    }
}

// -------- residual + LayerNorm + gamma/beta + mask + scatter ---------------
__global__ __launch_bounds__(256) void ln_kernel(
    const float* __restrict__ gamma, const float* __restrict__ beta,
    const int* __restrict__ a_starts, const int* __restrict__ a_sizes,
    float* __restrict__ out) {
    const int row = blockIdx.x;
    const int m = row / L;
    const int l = row - m * L;
    const int tid = threadIdx.x;   // 256 threads, 3 columns each

    __shared__ float redbuf[8];
    __shared__ float stat[2];

    float y[3];
    float s = 0.f;
#pragma unroll
    for (int i = 0; i < 3; i++) {
        int col = tid + i * 256;
        float v = g_Q[(size_t)row * H + col] + g_X[(size_t)row * H + col];
        y[i] = v;
        s += v;
    }
#pragma unroll
    for (int o = 16; o > 0; o >>= 1) s += __shfl_xor_sync(0xffffffffu, s, o);
    if ((tid & 31) == 0) redbuf[tid >> 5] = s;
    __syncthreads();
    if (tid == 0) {
        float t = 0.f;
#pragma unroll
        for (int i = 0; i < 8; i++) t += redbuf[i];
        stat[0] = t;
    }
    __syncthreads();
    const float mu = stat[0] * (1.f / 768.f);

    float vs = 0.f;
#pragma unroll
    for (int i = 0; i < 3; i++) {
        float d = y[i] - mu;
        vs += d * d;
    }
#pragma unroll
    for (int o = 16; o > 0; o >>= 1) vs += __shfl_xor_sync(0xffffffffu, vs, o);
    if ((tid & 31) == 0) redbuf[tid >> 5] = vs;
    __syncthreads();
    if (tid == 0) {
        float t = 0.f;
#pragma unroll
        for (int i = 0; i < 8; i++) t += redbuf[i];
        stat[1] = t;
    }
    __syncthreads();
    const float rstd = rsqrtf(stat[1] * (1.f / 768.f) + 1e-5f);

    const bool valid = l < a_sizes[m];
    const int dst = a_starts[m] + l;
#pragma unroll
    for (int i = 0; i < 3; i++) {
        int col = tid + i * 256;
        float o = valid ? ((y[i] - mu) * rstd * gamma[col] + beta[col]) : 0.f;
        out[(size_t)dst * H + col] = o;
    }
}

// ---------------------------------------------------------------------------
extern "C" void kernel_launch(void* const* d_in, const int* in_sizes, int n_in,
                              void* d_out, int out_size) {
    const float* atom     = (const float*)d_in[0];
    const float* Wq       = (const float*)d_in[1];
    const float* bq       = (const float*)d_in[2];
    const float* Wk       = (const float*)d_in[3];
    const float* bk       = (const float*)d_in[4];
    const float* Wv       = (const float*)d_in[5];
    const float* bv       = (const float*)d_in[6];
    const float* Wo       = (const float*)d_in[7];
    const float* bo       = (const float*)d_in[8];
    const float* gamma    = (const float*)d_in[9];
    const float* beta     = (const float*)d_in[10];
    const int*   a_starts = (const int*)d_in[11];
    const int*   a_sizes  = (const int*)d_in[12];
    float* out = (float*)d_out;

    float *pX, *pQ, *pK, *pV, *pC;
    cudaGetSymbolAddress((void**)&pX, g_X);
    cudaGetSymbolAddress((void**)&pQ, g_Q);
    cudaGetSymbolAddress((void**)&pK, g_K);
    cudaGetSymbolAddress((void**)&pV, g_V);
    cudaGetSymbolAddress((void**)&pC, g_C);

    const int attn_smem = 2 * L * HD * (int)sizeof(float);   // 128 KB
    cudaFuncSetAttribute(attn_kernel, cudaFuncAttributeMaxDynamicSharedMemorySize,
                         attn_smem);
    const int gemm_smem = 4 * 32 * SA * (int)sizeof(float);  // ~64.5 KB
    cudaFuncSetAttribute(gemm_tf32_kernel, cudaFuncAttributeMaxDynamicSharedMemorySize,
                         gemm_smem);

    // scatter semantics: rows not targeted stay zero
    cudaMemsetAsync(d_out, 0, (size_t)out_size * sizeof(float), 0);

    build_x_kernel<<<(NROWS * H / 4) / 256, 256>>>(atom, a_starts, a_sizes);

    dim3 ggrid(H / 128, NROWS / 128);
    gemm_tf32_kernel<<<ggrid, 256, gemm_smem>>>(pX, Wq, bq, pQ);
    gemm_tf32_kernel<<<ggrid, 256, gemm_smem>>>(pX, Wk, bk, pK);
    gemm_tf32_kernel<<<ggrid, 256, gemm_smem>>>(pX, Wv, bv, pV);

    attn_kernel<<<dim3(NH, MOLS), 256, attn_smem>>>(a_sizes);

    gemm_tf32_kernel<<<ggrid, 256, gemm_smem>>>(pC, Wo, bo, pQ);   // OUT reuses g_Q

    ln_kernel<<<NROWS, 256>>>(gamma, beta, a_starts, a_sizes, out);
}

// round 4
// speedup vs baseline: 1.8618x; 1.8146x over previous
#include <cuda_runtime.h>
#include <cuda_bf16.h>
#include <cstdint>

#define MOLS 128
#define L 256
#define H 768
#define NH 12
#define HD 64
#define NROWS (MOLS * L)

// ---- GEMM tiling ----
#define BM 128
#define BN 128
#define BK 32
#define KSTAGES (H / BK)     // 24
#define PIPE 3
#define ROWB 80              // padded smem row bytes (32 bf16 = 64B + 16B pad)
#define TILE_A (BM * ROWB)   // 10240
#define STAGE_BYTES (4 * TILE_A)           // Ahi, Alo, Bhi, Blo
#define GEMM_SMEM (PIPE * STAGE_BYTES)     // 122880

// ---------------- scratch (device globals) ---------------------------------
__device__ float g_X[(size_t)NROWS * H];   // masked input (fp32, for residual)
__device__ float g_Q[(size_t)NROWS * H];   // Q, later reused as OUT
__device__ float g_K[(size_t)NROWS * H];
__device__ float g_V[(size_t)NROWS * H];
__device__ __nv_bfloat16 g_Xhi[(size_t)NROWS * H];
__device__ __nv_bfloat16 g_Xlo[(size_t)NROWS * H];
__device__ __nv_bfloat16 g_Chi[(size_t)NROWS * H];
__device__ __nv_bfloat16 g_Clo[(size_t)NROWS * H];
__device__ __nv_bfloat16 g_Whi[4][(size_t)H * H];
__device__ __nv_bfloat16 g_Wlo[4][(size_t)H * H];

// ---------------- helpers ---------------------------------------------------
__device__ __forceinline__ uint32_t smem_u32(const void* p) {
    uint32_t a;
    asm("{ .reg .u64 t; cvta.to.shared.u64 t, %1; cvt.u32.u64 %0, t; }"
        : "=r"(a) : "l"(p));
    return a;
}
__device__ __forceinline__ void cvt_hilo2(float a, float b, uint32_t& hi, uint32_t& lo) {
    __nv_bfloat162 h = __float22bfloat162_rn(make_float2(a, b));
    float2 hf = __bfloat1622float2(h);
    __nv_bfloat162 l = __float22bfloat162_rn(make_float2(a - hf.x, b - hf.y));
    hi = *(uint32_t*)&h;
    lo = *(uint32_t*)&l;
}
__device__ __forceinline__ void cp16(uint32_t s, const void* g) {
    asm volatile("cp.async.cg.shared.global [%0], [%1], 16;" :: "r"(s), "l"(g));
}
#define CP_COMMIT() asm volatile("cp.async.commit_group;" ::: "memory")
#define CP_WAIT1()  asm volatile("cp.async.wait_group 1;" ::: "memory")
#define LDM4(r0, r1, r2, r3, addr) \
    asm volatile("ldmatrix.sync.aligned.m8n8.x4.shared.b16 {%0,%1,%2,%3}, [%4];" \
                 : "=r"(r0), "=r"(r1), "=r"(r2), "=r"(r3) : "r"(addr))
__device__ __forceinline__ void mma_bf16(float d[4], const uint32_t a[4],
                                         uint32_t b0, uint32_t b1) {
    asm volatile(
        "mma.sync.aligned.m16n8k16.row.col.f32.bf16.bf16.f32 "
        "{%0,%1,%2,%3}, {%4,%5,%6,%7}, {%8,%9}, {%0,%1,%2,%3};\n"
        : "+f"(d[0]), "+f"(d[1]), "+f"(d[2]), "+f"(d[3])
        : "r"(a[0]), "r"(a[1]), "r"(a[2]), "r"(a[3]), "r"(b0), "r"(b1));
}

// ---------------- masked gather + bf16 hi/lo split --------------------------
__global__ void build_x_kernel(const float* __restrict__ atom,
                               const int* __restrict__ a_starts,
                               const int* __restrict__ a_sizes) {
    int i = blockIdx.x * blockDim.x + threadIdx.x;     // float4 index
    const int W4 = H / 4;
    int row = i / W4;
    int c4  = (i - row * W4) * 4;
    int m = row / L;
    int l = row - m * L;
    float4 val = make_float4(0.f, 0.f, 0.f, 0.f);
    if (l < a_sizes[m]) {
        int src = a_starts[m] + l;
        val = *(const float4*)&atom[(size_t)src * H + c4];
    }
    size_t o = (size_t)row * H + c4;
    *(float4*)&g_X[o] = val;
    uint2 hi, lo;
    cvt_hilo2(val.x, val.y, hi.x, lo.x);
    cvt_hilo2(val.z, val.w, hi.y, lo.y);
    *(uint2*)&g_Xhi[o] = hi;
    *(uint2*)&g_Xlo[o] = lo;
}

// ---------------- weight fp32 -> bf16 hi/lo ---------------------------------
__global__ void cvt_w_kernel(const float* __restrict__ W,
                             __nv_bfloat16* __restrict__ hi,
                             __nv_bfloat16* __restrict__ lo) {
    int i = blockIdx.x * blockDim.x + threadIdx.x;     // float4 index
    float4 v = ((const float4*)W)[i];
    uint2 h, l;
    cvt_hilo2(v.x, v.y, h.x, l.x);
    cvt_hilo2(v.z, v.w, h.y, l.y);
    ((uint2*)hi)[i] = h;
    ((uint2*)lo)[i] = l;
}

// ---------------- bf16 compensated GEMM: C[n,o] = X·Wᵗ + bias ---------------
// C = Ahi·Bhiᵗ + Ahi·Bloᵗ + Alo·Bhiᵗ  (fp32 accum via mma.m16n8k16)
__global__ __launch_bounds__(256, 1) void gemm_bf16_kernel(
    const __nv_bfloat16* __restrict__ Ahi, const __nv_bfloat16* __restrict__ Alo,
    const __nv_bfloat16* __restrict__ Bhi, const __nv_bfloat16* __restrict__ Blo,
    const float* __restrict__ bias, float* __restrict__ C) {
    extern __shared__ char sm[];
    const uint32_t smb = smem_u32(sm);
    const int tid = threadIdx.x;
    const int lane = tid & 31;
    const int wid = tid >> 5;
    const int wm = wid >> 2;            // 0..1
    const int wn = wid & 3;             // 0..3
    const int bm = blockIdx.y * BM;
    const int bn = blockIdx.x * BN;

    float acc[4][4][4];
#pragma unroll
    for (int i = 0; i < 4; i++)
#pragma unroll
        for (int j = 0; j < 4; j++)
#pragma unroll
            for (int t = 0; t < 4; t++) acc[i][j][t] = 0.f;

    // per-thread staging chunks: 2 x 16B for each of Ahi/Alo/Bhi/Blo
    const int c0 = tid * 2;            // chunk ids c0, c0+1  (512 total)
    const int r0 = c0 >> 2, kc0 = (c0 & 3);
    const int r1 = (c0 + 1) >> 2, kc1 = ((c0 + 1) & 3);

    auto load_stage = [&](int buf, int k0) {
        uint32_t sb = smb + buf * STAGE_BYTES;
        size_t ga0 = (size_t)(bm + r0) * H + k0 + kc0 * 8;
        size_t ga1 = (size_t)(bm + r1) * H + k0 + kc1 * 8;
        size_t gb0 = (size_t)(bn + r0) * H + k0 + kc0 * 8;
        size_t gb1 = (size_t)(bn + r1) * H + k0 + kc1 * 8;
        uint32_t s0 = r0 * ROWB + kc0 * 16;
        uint32_t s1 = r1 * ROWB + kc1 * 16;
        cp16(sb + s0, Ahi + ga0);
        cp16(sb + s1, Ahi + ga1);
        cp16(sb + TILE_A + s0, Alo + ga0);
        cp16(sb + TILE_A + s1, Alo + ga1);
        cp16(sb + 2 * TILE_A + s0, Bhi + gb0);
        cp16(sb + 2 * TILE_A + s1, Bhi + gb1);
        cp16(sb + 3 * TILE_A + s0, Blo + gb0);
        cp16(sb + 3 * TILE_A + s1, Blo + gb1);
    };

    load_stage(0, 0);
    CP_COMMIT();
    load_stage(1, BK);
    CP_COMMIT();

    const int trow = lane & 15;
    const int tkb = (lane >> 4) * 16;

#pragma unroll 1
    for (int ks = 0; ks < KSTAGES; ks++) {
        CP_WAIT1();
        __syncthreads();
        int nxt = ks + 2;
        if (nxt < KSTAGES) load_stage(nxt % PIPE, nxt * BK);
        CP_COMMIT();

        const uint32_t sA = smb + (ks % PIPE) * STAGE_BYTES;
        const uint32_t sB = sA + 2 * TILE_A;
#pragma unroll
        for (int kh = 0; kh < 2; kh++) {
            const uint32_t koff = kh * 32 + tkb;
            uint32_t ah[4][4], al[4][4], bh[2][4], bl[2][4];
#pragma unroll
            for (int mt = 0; mt < 4; mt++) {
                uint32_t a = sA + (wm * 64 + mt * 16 + trow) * ROWB + koff;
                LDM4(ah[mt][0], ah[mt][1], ah[mt][2], ah[mt][3], a);
                LDM4(al[mt][0], al[mt][1], al[mt][2], al[mt][3], a + TILE_A);
            }
#pragma unroll
            for (int g = 0; g < 2; g++) {
                uint32_t b = sB + (wn * 32 + g * 16 + trow) * ROWB + koff;
                LDM4(bh[g][0], bh[g][1], bh[g][2], bh[g][3], b);
                LDM4(bl[g][0], bl[g][1], bl[g][2], bl[g][3], b + TILE_A);
            }
#pragma unroll
            for (int mt = 0; mt < 4; mt++)
#pragma unroll
                for (int nt = 0; nt < 4; nt++) {
                    const int g = nt >> 1, s = nt & 1;
                    mma_bf16(acc[mt][nt], ah[mt], bh[g][s], bh[g][s + 2]);
                    mma_bf16(acc[mt][nt], ah[mt], bl[g][s], bl[g][s + 2]);
                    mma_bf16(acc[mt][nt], al[mt], bh[g][s], bh[g][s + 2]);
                }
        }
    }

#pragma unroll
    for (int mt = 0; mt < 4; mt++) {
        int row = bm + wm * 64 + mt * 16 + (lane >> 2);
#pragma unroll
        for (int nt = 0; nt < 4; nt++) {
            int col = bn + wn * 32 + nt * 8 + (lane & 3) * 2;
            float2 bb = *(const float2*)&bias[col];
            float* p = C + (size_t)row * H + col;
            *(float2*)p = make_float2(acc[mt][nt][0] + bb.x, acc[mt][nt][1] + bb.y);
            *(float2*)(p + 8 * H) =
                make_float2(acc[mt][nt][2] + bb.x, acc[mt][nt][3] + bb.y);
        }
    }
}

// ---------------- attention: one CTA per (head, molecule) ------------------
// Writes context directly as bf16 hi/lo (consumed by the O-projection GEMM).
__global__ __launch_bounds__(256, 1) void attn_kernel(const int* __restrict__ a_sizes) {
    extern __shared__ float smf[];
    float* Ks = smf;
    float* Vs = smf + L * HD;
    const int h = blockIdx.x, m = blockIdx.y;
    const int tid = threadIdx.x;
    const int size = a_sizes[m];

    for (int i = tid; i < L * HD / 4; i += 256) {
        int r = i >> 4;
        int c = (i & 15) << 2;
        size_t src = (size_t)(m * L + r) * H + h * HD + c;
        *(float4*)&Ks[r * HD + c] = *(const float4*)&g_K[src];
        *(float4*)&Vs[r * HD + c] = *(const float4*)&g_V[src];
    }
    __syncthreads();

    const int q = tid;
    float qr[HD];
    {
        const float* Qrow = &g_Q[(size_t)(m * L + q) * H + h * HD];
#pragma unroll
        for (int d = 0; d < HD; d += 4) {
            float4 t = *(const float4*)&Qrow[d];
            qr[d] = t.x; qr[d + 1] = t.y; qr[d + 2] = t.z; qr[d + 3] = t.w;
        }
    }
    const float scale = 0.125f;

    float acc[HD];
#pragma unroll
    for (int d = 0; d < HD; d++) acc[d] = 0.f;
    float mx = -1e30f;
    float sum = 0.f;

    for (int k = 0; k < size; k++) {
        const float* kr = &Ks[k * HD];
        float s = 0.f;
#pragma unroll
        for (int d = 0; d < HD; d++) s = fmaf(qr[d], kr[d], s);
        s *= scale;
        if (s > mx) {
            float f = __expf(mx - s);
            sum *= f;
#pragma unroll
            for (int d = 0; d < HD; d++) acc[d] *= f;
            mx = s;
        }
        float p = __expf(s - mx);
        sum += p;
        const float* vr = &Vs[k * HD];
#pragma unroll
        for (int d = 0; d < HD; d++) acc[d] = fmaf(p, vr[d], acc[d]);
    }
    float inv = 1.f / sum;
    size_t o = (size_t)(m * L + q) * H + h * HD;
#pragma unroll
    for (int d = 0; d < HD; d += 4) {
        float o0 = acc[d] * inv, o1 = acc[d + 1] * inv;
        float o2 = acc[d + 2] * inv, o3 = acc[d + 3] * inv;
        uint2 hi, lo;
        cvt_hilo2(o0, o1, hi.x, lo.x);
        cvt_hilo2(o2, o3, hi.y, lo.y);
        *(uint2*)&g_Chi[o + d] = hi;
        *(uint2*)&g_Clo[o + d] = lo;
    }
}

// -------- residual + LayerNorm + gamma/beta + mask + scatter ---------------
__global__ __launch_bounds__(256) void ln_kernel(
    const float* __restrict__ gamma, const float* __restrict__ beta,
    const int* __restrict__ a_starts, const int* __restrict__ a_sizes,
    float* __restrict__ out) {
    const int row = blockIdx.x;
    const int m = row / L;
    const int l = row - m * L;
    const int tid = threadIdx.x;

    __shared__ float redbuf[8];
    __shared__ float stat[2];

    float y[3];
    float s = 0.f;
#pragma unroll
    for (int i = 0; i < 3; i++) {
        int col = tid + i * 256;
        float v = g_Q[(size_t)row * H + col] + g_X[(size_t)row * H + col];
        y[i] = v;
        s += v;
    }
#pragma unroll
    for (int o = 16; o > 0; o >>= 1) s += __shfl_xor_sync(0xffffffffu, s, o);
    if ((tid & 31) == 0) redbuf[tid >> 5] = s;
    __syncthreads();
    if (tid == 0) {
        float t = 0.f;
#pragma unroll
        for (int i = 0; i < 8; i++) t += redbuf[i];
        stat[0] = t;
    }
    __syncthreads();
    const float mu = stat[0] * (1.f / 768.f);

    float vs = 0.f;
#pragma unroll
    for (int i = 0; i < 3; i++) {
        float d = y[i] - mu;
        vs += d * d;
    }
#pragma unroll
    for (int o = 16; o > 0; o >>= 1) vs += __shfl_xor_sync(0xffffffffu, vs, o);
    if ((tid & 31) == 0) redbuf[tid >> 5] = vs;
    __syncthreads();
    if (tid == 0) {
        float t = 0.f;
#pragma unroll
        for (int i = 0; i < 8; i++) t += redbuf[i];
        stat[1] = t;
    }
    __syncthreads();
    const float rstd = rsqrtf(stat[1] * (1.f / 768.f) + 1e-5f);

    const bool valid = l < a_sizes[m];
    const int dst = a_starts[m] + l;
#pragma unroll
    for (int i = 0; i < 3; i++) {
        int col = tid + i * 256;
        float o = valid ? ((y[i] - mu) * rstd * gamma[col] + beta[col]) : 0.f;
        out[(size_t)dst * H + col] = o;
    }
}

// ---------------------------------------------------------------------------
extern "C" void kernel_launch(void* const* d_in, const int* in_sizes, int n_in,
                              void* d_out, int out_size) {
    const float* atom     = (const float*)d_in[0];
    const float* Wq       = (const float*)d_in[1];
    const float* bq       = (const float*)d_in[2];
    const float* Wk       = (const float*)d_in[3];
    const float* bk       = (const float*)d_in[4];
    const float* Wv       = (const float*)d_in[5];
    const float* bv       = (const float*)d_in[6];
    const float* Wo       = (const float*)d_in[7];
    const float* bo       = (const float*)d_in[8];
    const float* gamma    = (const float*)d_in[9];
    const float* beta     = (const float*)d_in[10];
    const int*   a_starts = (const int*)d_in[11];
    const int*   a_sizes  = (const int*)d_in[12];
    float* out = (float*)d_out;

    float *pX, *pQ, *pK, *pV;
    __nv_bfloat16 *pXhi, *pXlo, *pChi, *pClo, *pWhi, *pWlo;
    cudaGetSymbolAddress((void**)&pX, g_X);
    cudaGetSymbolAddress((void**)&pQ, g_Q);
    cudaGetSymbolAddress((void**)&pK, g_K);
    cudaGetSymbolAddress((void**)&pV, g_V);
    cudaGetSymbolAddress((void**)&pXhi, g_Xhi);
    cudaGetSymbolAddress((void**)&pXlo, g_Xlo);
    cudaGetSymbolAddress((void**)&pChi, g_Chi);
    cudaGetSymbolAddress((void**)&pClo, g_Clo);
    cudaGetSymbolAddress((void**)&pWhi, g_Whi);
    cudaGetSymbolAddress((void**)&pWlo, g_Wlo);
    const size_t WSZ = (size_t)H * H;

    const int attn_smem = 2 * L * HD * (int)sizeof(float);   // 128 KB
    cudaFuncSetAttribute(attn_kernel, cudaFuncAttributeMaxDynamicSharedMemorySize,
                         attn_smem);
    cudaFuncSetAttribute(gemm_bf16_kernel, cudaFuncAttributeMaxDynamicSharedMemorySize,
                         GEMM_SMEM);

    cudaMemsetAsync(d_out, 0, (size_t)out_size * sizeof(float), 0);

    build_x_kernel<<<(NROWS * H / 4) / 256, 256>>>(atom, a_starts, a_sizes);
    const int wblocks = (H * H / 4) / 256;   // 576
    cvt_w_kernel<<<wblocks, 256>>>(Wq, pWhi + 0 * WSZ, pWlo + 0 * WSZ);
    cvt_w_kernel<<<wblocks, 256>>>(Wk, pWhi + 1 * WSZ, pWlo + 1 * WSZ);
    cvt_w_kernel<<<wblocks, 256>>>(Wv, pWhi + 2 * WSZ, pWlo + 2 * WSZ);
    cvt_w_kernel<<<wblocks, 256>>>(Wo, pWhi + 3 * WSZ, pWlo + 3 * WSZ);

    dim3 ggrid(H / BN, NROWS / BM);    // (6, 256)
    gemm_bf16_kernel<<<ggrid, 256, GEMM_SMEM>>>(pXhi, pXlo, pWhi + 0 * WSZ,
                                                pWlo + 0 * WSZ, bq, pQ);
    gemm_bf16_kernel<<<ggrid, 256, GEMM_SMEM>>>(pXhi, pXlo, pWhi + 1 * WSZ,
                                                pWlo + 1 * WSZ, bk, pK);
    gemm_bf16_kernel<<<ggrid, 256, GEMM_SMEM>>>(pXhi, pXlo, pWhi + 2 * WSZ,
                                                pWlo + 2 * WSZ, bv, pV);

    attn_kernel<<<dim3(NH, MOLS), 256, attn_smem>>>(a_sizes);

    gemm_bf16_kernel<<<ggrid, 256, GEMM_SMEM>>>(pChi, pClo, pWhi + 3 * WSZ,
                                                pWlo + 3 * WSZ, bo, pQ);

    ln_kernel<<<NROWS, 256>>>(gamma, beta, a_starts, a_sizes, out);
}

// round 5
// speedup vs baseline: 2.3384x; 1.2560x over previous
#include <cuda_runtime.h>
#include <cuda_bf16.h>
#include <cstdint>

#define MOLS 128
#define L 256
#define H 768
#define NH 12
#define HD 64
#define NROWS (MOLS * L)

// ---- GEMM tiling ----
#define BM 128
#define BN 128
#define BK 32
#define KSTAGES (H / BK)     // 24
#define PIPE 3
#define ROWB 80              // padded smem row bytes (32 bf16 = 64B + 16B pad)
#define TILE_A (BM * ROWB)   // 10240
#define STAGE_BYTES (4 * TILE_A)           // Ahi, Alo, Bhi, Blo
#define GEMM_SMEM (PIPE * STAGE_BYTES)     // 122880

// ---- attention smem layout (bytes) ----
#define ATT_KHI 0
#define ATT_KLO 36864                      // 256 rows * 144
#define ATT_VHI 73728
#define ATT_VLO 107520                     // 64 rows * 528
#define ATT_SMEM 141312

// ---------------- scratch (device globals) ---------------------------------
__device__ float g_X[(size_t)NROWS * H];   // masked input (fp32, for residual)
__device__ float g_Q[(size_t)NROWS * H];   // Q, later reused as OUT
__device__ float g_K[(size_t)NROWS * H];
__device__ float g_V[(size_t)NROWS * H];
__device__ __nv_bfloat16 g_Xhi[(size_t)NROWS * H];
__device__ __nv_bfloat16 g_Xlo[(size_t)NROWS * H];
__device__ __nv_bfloat16 g_Chi[(size_t)NROWS * H];
__device__ __nv_bfloat16 g_Clo[(size_t)NROWS * H];
__device__ __nv_bfloat16 g_Whi[4][(size_t)H * H];
__device__ __nv_bfloat16 g_Wlo[4][(size_t)H * H];

// ---------------- helpers ---------------------------------------------------
__device__ __forceinline__ uint32_t smem_u32(const void* p) {
    uint32_t a;
    asm("{ .reg .u64 t; cvta.to.shared.u64 t, %1; cvt.u32.u64 %0, t; }"
        : "=r"(a) : "l"(p));
    return a;
}
__device__ __forceinline__ void cvt_hilo2(float a, float b, uint32_t& hi, uint32_t& lo) {
    __nv_bfloat162 h = __float22bfloat162_rn(make_float2(a, b));
    float2 hf = __bfloat1622float2(h);
    __nv_bfloat162 l = __float22bfloat162_rn(make_float2(a - hf.x, b - hf.y));
    hi = *(uint32_t*)&h;
    lo = *(uint32_t*)&l;
}
__device__ __forceinline__ float ex2(float x) {
    float y;
    asm("ex2.approx.ftz.f32 %0, %1;" : "=f"(y) : "f"(x));
    return y;
}
__device__ __forceinline__ void cp16(uint32_t s, const void* g) {
    asm volatile("cp.async.cg.shared.global [%0], [%1], 16;" :: "r"(s), "l"(g));
}
#define CP_COMMIT() asm volatile("cp.async.commit_group;" ::: "memory")
#define CP_WAIT1()  asm volatile("cp.async.wait_group 1;" ::: "memory")
#define LDM4(r0, r1, r2, r3, addr) \
    asm volatile("ldmatrix.sync.aligned.m8n8.x4.shared.b16 {%0,%1,%2,%3}, [%4];" \
                 : "=r"(r0), "=r"(r1), "=r"(r2), "=r"(r3) : "r"(addr))
__device__ __forceinline__ void mma_bf16(float d[4], const uint32_t a[4],
                                         uint32_t b0, uint32_t b1) {
    asm volatile(
        "mma.sync.aligned.m16n8k16.row.col.f32.bf16.bf16.f32 "
        "{%0,%1,%2,%3}, {%4,%5,%6,%7}, {%8,%9}, {%0,%1,%2,%3};\n"
        : "+f"(d[0]), "+f"(d[1]), "+f"(d[2]), "+f"(d[3])
        : "r"(a[0]), "r"(a[1]), "r"(a[2]), "r"(a[3]), "r"(b0), "r"(b1));
}

// ---------------- masked gather + bf16 hi/lo split --------------------------
__global__ void build_x_kernel(const float* __restrict__ atom,
                               const int* __restrict__ a_starts,
                               const int* __restrict__ a_sizes) {
    int i = blockIdx.x * blockDim.x + threadIdx.x;     // float4 index
    const int W4 = H / 4;
    int row = i / W4;
    int c4  = (i - row * W4) * 4;
    int m = row / L;
    int l = row - m * L;
    float4 val = make_float4(0.f, 0.f, 0.f, 0.f);
    if (l < a_sizes[m]) {
        int src = a_starts[m] + l;
        val = *(const float4*)&atom[(size_t)src * H + c4];
    }
    size_t o = (size_t)row * H + c4;
    *(float4*)&g_X[o] = val;
    uint2 hi, lo;
    cvt_hilo2(val.x, val.y, hi.x, lo.x);
    cvt_hilo2(val.z, val.w, hi.y, lo.y);
    *(uint2*)&g_Xhi[o] = hi;
    *(uint2*)&g_Xlo[o] = lo;
}

// ---------------- weight fp32 -> bf16 hi/lo ---------------------------------
__global__ void cvt_w_kernel(const float* __restrict__ W,
                             __nv_bfloat16* __restrict__ hi,
                             __nv_bfloat16* __restrict__ lo) {
    int i = blockIdx.x * blockDim.x + threadIdx.x;     // float4 index
    float4 v = ((const float4*)W)[i];
    uint2 h, l;
    cvt_hilo2(v.x, v.y, h.x, l.x);
    cvt_hilo2(v.z, v.w, h.y, l.y);
    ((uint2*)hi)[i] = h;
    ((uint2*)lo)[i] = l;
}

// ---------------- bf16 compensated GEMM: C[n,o] = X·Wᵗ + bias ---------------
__global__ __launch_bounds__(256, 1) void gemm_bf16_kernel(
    const __nv_bfloat16* __restrict__ Ahi, const __nv_bfloat16* __restrict__ Alo,
    const __nv_bfloat16* __restrict__ Bhi, const __nv_bfloat16* __restrict__ Blo,
    const float* __restrict__ bias, float* __restrict__ C) {
    extern __shared__ char sm[];
    const uint32_t smb = smem_u32(sm);
    const int tid = threadIdx.x;
    const int lane = tid & 31;
    const int wid = tid >> 5;
    const int wm = wid >> 2;            // 0..1
    const int wn = wid & 3;             // 0..3
    const int bm = blockIdx.y * BM;
    const int bn = blockIdx.x * BN;

    float acc[4][4][4];
#pragma unroll
    for (int i = 0; i < 4; i++)
#pragma unroll
        for (int j = 0; j < 4; j++)
#pragma unroll
            for (int t = 0; t < 4; t++) acc[i][j][t] = 0.f;

    const int c0 = tid * 2;
    const int r0 = c0 >> 2, kc0 = (c0 & 3);
    const int r1 = (c0 + 1) >> 2, kc1 = ((c0 + 1) & 3);

    auto load_stage = [&](int buf, int k0) {
        uint32_t sb = smb + buf * STAGE_BYTES;
        size_t ga0 = (size_t)(bm + r0) * H + k0 + kc0 * 8;
        size_t ga1 = (size_t)(bm + r1) * H + k0 + kc1 * 8;
        size_t gb0 = (size_t)(bn + r0) * H + k0 + kc0 * 8;
        size_t gb1 = (size_t)(bn + r1) * H + k0 + kc1 * 8;
        uint32_t s0 = r0 * ROWB + kc0 * 16;
        uint32_t s1 = r1 * ROWB + kc1 * 16;
        cp16(sb + s0, Ahi + ga0);
        cp16(sb + s1, Ahi + ga1);
        cp16(sb + TILE_A + s0, Alo + ga0);
        cp16(sb + TILE_A + s1, Alo + ga1);
        cp16(sb + 2 * TILE_A + s0, Bhi + gb0);
        cp16(sb + 2 * TILE_A + s1, Bhi + gb1);
        cp16(sb + 3 * TILE_A + s0, Blo + gb0);
        cp16(sb + 3 * TILE_A + s1, Blo + gb1);
    };

    load_stage(0, 0);
    CP_COMMIT();
    load_stage(1, BK);
    CP_COMMIT();

    const int trow = lane & 15;
    const int tkb = (lane >> 4) * 16;

#pragma unroll 1
    for (int ks = 0; ks < KSTAGES; ks++) {
        CP_WAIT1();
        __syncthreads();
        int nxt = ks + 2;
        if (nxt < KSTAGES) load_stage(nxt % PIPE, nxt * BK);
        CP_COMMIT();

        const uint32_t sA = smb + (ks % PIPE) * STAGE_BYTES;
        const uint32_t sB = sA + 2 * TILE_A;
#pragma unroll
        for (int kh = 0; kh < 2; kh++) {
            const uint32_t koff = kh * 32 + tkb;
            uint32_t ah[4][4], al[4][4], bh[2][4], bl[2][4];
#pragma unroll
            for (int mt = 0; mt < 4; mt++) {
                uint32_t a = sA + (wm * 64 + mt * 16 + trow) * ROWB + koff;
                LDM4(ah[mt][0], ah[mt][1], ah[mt][2], ah[mt][3], a);
                LDM4(al[mt][0], al[mt][1], al[mt][2], al[mt][3], a + TILE_A);
            }
#pragma unroll
            for (int g = 0; g < 2; g++) {
                uint32_t b = sB + (wn * 32 + g * 16 + trow) * ROWB + koff;
                LDM4(bh[g][0], bh[g][1], bh[g][2], bh[g][3], b);
                LDM4(bl[g][0], bl[g][1], bl[g][2], bl[g][3], b + TILE_A);
            }
#pragma unroll
            for (int mt = 0; mt < 4; mt++)
#pragma unroll
                for (int nt = 0; nt < 4; nt++) {
                    const int g = nt >> 1, s = nt & 1;
                    mma_bf16(acc[mt][nt], ah[mt], bh[g][s], bh[g][s + 2]);
                    mma_bf16(acc[mt][nt], ah[mt], bl[g][s], bl[g][s + 2]);
                    mma_bf16(acc[mt][nt], al[mt], bh[g][s], bh[g][s + 2]);
                }
        }
    }

#pragma unroll
    for (int mt = 0; mt < 4; mt++) {
        int row = bm + wm * 64 + mt * 16 + (lane >> 2);
#pragma unroll
        for (int nt = 0; nt < 4; nt++) {
            int col = bn + wn * 32 + nt * 8 + (lane & 3) * 2;
            float2 bb = *(const float2*)&bias[col];
            float* p = C + (size_t)row * H + col;
            *(float2*)p = make_float2(acc[mt][nt][0] + bb.x, acc[mt][nt][1] + bb.y);
            *(float2*)(p + 8 * H) =
                make_float2(acc[mt][nt][2] + bb.x, acc[mt][nt][3] + bb.y);
        }
    }
}

// ---------------- tensor-core flash attention -------------------------------
// CTA = (head, molecule, q-half of 128 rows); warp = 16 query rows.
// K [256,64] and V^T [64,256] staged in smem as bf16 hi/lo.
// QK and PV are 3-term compensated bf16 mma; online softmax in log2 domain.
__global__ __launch_bounds__(256, 1) void attn_tc_kernel(const int* __restrict__ a_sizes) {
    extern __shared__ char sm[];
    const uint32_t smb = smem_u32(sm);
    const int h = blockIdx.x, m = blockIdx.y;
    const int tid = threadIdx.x;
    const int lane = tid & 31;
    const int wid = tid >> 5;
    const int size = a_sizes[m];

    // ---- stage K: rows = key j (144B pitch), cols = d, bf16 hi/lo ----
#pragma unroll
    for (int it = 0; it < 16; it++) {
        int i = tid + it * 256;
        int row = i >> 4, c4 = (i & 15) * 4;
        float4 v = *(const float4*)&g_K[(size_t)(m * L + row) * H + h * HD + c4];
        uint2 hi, lo;
        cvt_hilo2(v.x, v.y, hi.x, lo.x);
        cvt_hilo2(v.z, v.w, hi.y, lo.y);
        *(uint2*)(sm + ATT_KHI + row * 144 + c4 * 2) = hi;
        *(uint2*)(sm + ATT_KLO + row * 144 + c4 * 2) = lo;
    }
    // ---- stage V^T: rows = d (528B pitch), cols = key j ----
#pragma unroll
    for (int it = 0; it < 32; it++) {
        int p = tid + it * 256;
        int d = p & 63, j = (p >> 6) * 2;
        float v0 = g_V[(size_t)(m * L + j) * H + h * HD + d];
        float v1 = g_V[(size_t)(m * L + j + 1) * H + h * HD + d];
        uint32_t hi, lo;
        cvt_hilo2(v0, v1, hi, lo);
        *(uint32_t*)(sm + ATT_VHI + d * 528 + j * 2) = hi;
        *(uint32_t*)(sm + ATT_VLO + d * 528 + j * 2) = lo;
    }
    __syncthreads();

    const int tq2 = (lane & 3) * 2;
    const int l15 = lane & 15;
    const int lhk = (lane >> 4) * 16;
    const int row0 = blockIdx.z * 128 + wid * 16 + (lane >> 2);
    const float scale2 = 0.125f * 1.4426950408889634f;   // HD^-0.5 * log2(e)

    // Q fragments (scale pre-folded), hi/lo
    uint32_t qhi[4][4], qlo[4][4];
    {
        const float* qp = &g_Q[(size_t)(m * L + row0) * H + h * HD];
#pragma unroll
        for (int ks = 0; ks < 4; ks++) {
            int k = ks * 16 + tq2;
            float2 a = *(const float2*)(qp + k);
            float2 b = *(const float2*)(qp + 8 * H + k);
            float2 c = *(const float2*)(qp + k + 8);
            float2 d = *(const float2*)(qp + 8 * H + k + 8);
            cvt_hilo2(a.x * scale2, a.y * scale2, qhi[ks][0], qlo[ks][0]);
            cvt_hilo2(b.x * scale2, b.y * scale2, qhi[ks][1], qlo[ks][1]);
            cvt_hilo2(c.x * scale2, c.y * scale2, qhi[ks][2], qlo[ks][2]);
            cvt_hilo2(d.x * scale2, d.y * scale2, qhi[ks][3], qlo[ks][3]);
        }
    }

    float O[8][4];
#pragma unroll
    for (int i = 0; i < 8; i++)
#pragma unroll
        for (int j = 0; j < 4; j++) O[i][j] = 0.f;
    float m0 = -1e30f, m1 = -1e30f, l0 = 0.f, l1 = 0.f;

    const int nch = min(4, (size + 63) >> 6);
#pragma unroll 1
    for (int c = 0; c < nch; c++) {
        const int j0 = c * 64;
        float S[8][4];
#pragma unroll
        for (int i = 0; i < 8; i++)
#pragma unroll
            for (int j = 0; j < 4; j++) S[i][j] = 0.f;

        // ---- QK: S = Q'·K^T (log2 domain) ----
#pragma unroll
        for (int np = 0; np < 4; np++) {
            uint32_t kra = smb + ATT_KHI + (j0 + np * 16 + l15) * 144 + lhk;
#pragma unroll
            for (int ks = 0; ks < 4; ks++) {
                uint32_t kh0, kh1, kh2, kh3, kl0, kl1, kl2, kl3;
                LDM4(kh0, kh1, kh2, kh3, kra + ks * 32);
                LDM4(kl0, kl1, kl2, kl3, kra + ks * 32 + (ATT_KLO - ATT_KHI));
                mma_bf16(S[2 * np], qhi[ks], kh0, kh2);
                mma_bf16(S[2 * np], qlo[ks], kh0, kh2);
                mma_bf16(S[2 * np], qhi[ks], kl0, kl2);
                mma_bf16(S[2 * np + 1], qhi[ks], kh1, kh3);
                mma_bf16(S[2 * np + 1], qlo[ks], kh1, kh3);
                mma_bf16(S[2 * np + 1], qhi[ks], kl1, kl3);
            }
        }

        // ---- mask boundary chunk ----
        if (j0 + 64 > size) {
#pragma unroll
            for (int nt = 0; nt < 8; nt++) {
                int col = j0 + nt * 8 + tq2;
                if (col >= size)     { S[nt][0] = -1e30f; S[nt][2] = -1e30f; }
                if (col + 1 >= size) { S[nt][1] = -1e30f; S[nt][3] = -1e30f; }
            }
        }

        // ---- online softmax on fragments ----
        float mx0 = -1e30f, mx1 = -1e30f;
#pragma unroll
        for (int nt = 0; nt < 8; nt++) {
            mx0 = fmaxf(mx0, fmaxf(S[nt][0], S[nt][1]));
            mx1 = fmaxf(mx1, fmaxf(S[nt][2], S[nt][3]));
        }
        mx0 = fmaxf(mx0, __shfl_xor_sync(0xffffffffu, mx0, 1));
        mx0 = fmaxf(mx0, __shfl_xor_sync(0xffffffffu, mx0, 2));
        mx1 = fmaxf(mx1, __shfl_xor_sync(0xffffffffu, mx1, 1));
        mx1 = fmaxf(mx1, __shfl_xor_sync(0xffffffffu, mx1, 2));
        float nm0 = fmaxf(m0, mx0), nm1 = fmaxf(m1, mx1);
        float f0 = ex2(m0 - nm0), f1 = ex2(m1 - nm1);
        float rs0 = 0.f, rs1 = 0.f;
#pragma unroll
        for (int nt = 0; nt < 8; nt++) {
            S[nt][0] = ex2(S[nt][0] - nm0); rs0 += S[nt][0];
            S[nt][1] = ex2(S[nt][1] - nm0); rs0 += S[nt][1];
            S[nt][2] = ex2(S[nt][2] - nm1); rs1 += S[nt][2];
            S[nt][3] = ex2(S[nt][3] - nm1); rs1 += S[nt][3];
        }
        rs0 += __shfl_xor_sync(0xffffffffu, rs0, 1);
        rs0 += __shfl_xor_sync(0xffffffffu, rs0, 2);
        rs1 += __shfl_xor_sync(0xffffffffu, rs1, 1);
        rs1 += __shfl_xor_sync(0xffffffffu, rs1, 2);
        l0 = l0 * f0 + rs0;
        l1 = l1 * f1 + rs1;
        m0 = nm0; m1 = nm1;
#pragma unroll
        for (int dt = 0; dt < 8; dt++) {
            O[dt][0] *= f0; O[dt][1] *= f0;
            O[dt][2] *= f1; O[dt][3] *= f1;
        }

        // ---- P fragments (bf16 hi/lo) ----
        uint32_t phi[4][4], plo[4][4];
#pragma unroll
        for (int ks = 0; ks < 4; ks++) {
            cvt_hilo2(S[2 * ks][0], S[2 * ks][1], phi[ks][0], plo[ks][0]);
            cvt_hilo2(S[2 * ks][2], S[2 * ks][3], phi[ks][1], plo[ks][1]);
            cvt_hilo2(S[2 * ks + 1][0], S[2 * ks + 1][1], phi[ks][2], plo[ks][2]);
            cvt_hilo2(S[2 * ks + 1][2], S[2 * ks + 1][3], phi[ks][3], plo[ks][3]);
        }

        // ---- PV: O += P·V ----
#pragma unroll
        for (int dp = 0; dp < 4; dp++) {
            uint32_t vra = smb + ATT_VHI + (dp * 16 + l15) * 528 + j0 * 2 + lhk;
#pragma unroll
            for (int ks = 0; ks < 4; ks++) {
                uint32_t vh0, vh1, vh2, vh3, vl0, vl1, vl2, vl3;
                LDM4(vh0, vh1, vh2, vh3, vra + ks * 32);
                LDM4(vl0, vl1, vl2, vl3, vra + ks * 32 + (ATT_VLO - ATT_VHI));
                mma_bf16(O[2 * dp], phi[ks], vh0, vh2);
                mma_bf16(O[2 * dp], plo[ks], vh0, vh2);
                mma_bf16(O[2 * dp], phi[ks], vl0, vl2);
                mma_bf16(O[2 * dp + 1], phi[ks], vh1, vh3);
                mma_bf16(O[2 * dp + 1], plo[ks], vh1, vh3);
                mma_bf16(O[2 * dp + 1], phi[ks], vl1, vl3);
            }
        }
    }

    // ---- normalize + write ctx as bf16 hi/lo ----
    const float i0 = 1.f / l0, i1 = 1.f / l1;
    const size_t ob = (size_t)(m * L + row0) * H + h * HD + tq2;
#pragma unroll
    for (int dt = 0; dt < 8; dt++) {
        uint32_t hi, lo;
        cvt_hilo2(O[dt][0] * i0, O[dt][1] * i0, hi, lo);
        *(uint32_t*)&g_Chi[ob + dt * 8] = hi;
        *(uint32_t*)&g_Clo[ob + dt * 8] = lo;
        cvt_hilo2(O[dt][2] * i1, O[dt][3] * i1, hi, lo);
        *(uint32_t*)&g_Chi[ob + 8 * H + dt * 8] = hi;
        *(uint32_t*)&g_Clo[ob + 8 * H + dt * 8] = lo;
    }
}

// -------- residual + LayerNorm + gamma/beta + mask + scatter ---------------
__global__ __launch_bounds__(256) void ln_kernel(
    const float* __restrict__ gamma, const float* __restrict__ beta,
    const int* __restrict__ a_starts, const int* __restrict__ a_sizes,
    float* __restrict__ out) {
    const int row = blockIdx.x;
    const int m = row / L;
    const int l = row - m * L;
    const int tid = threadIdx.x;

    __shared__ float redbuf[8];
    __shared__ float stat[2];

    float y[3];
    float s = 0.f;
#pragma unroll
    for (int i = 0; i < 3; i++) {
        int col = tid + i * 256;
        float v = g_Q[(size_t)row * H + col] + g_X[(size_t)row * H + col];
        y[i] = v;
        s += v;
    }
#pragma unroll
    for (int o = 16; o > 0; o >>= 1) s += __shfl_xor_sync(0xffffffffu, s, o);
    if ((tid & 31) == 0) redbuf[tid >> 5] = s;
    __syncthreads();
    if (tid == 0) {
        float t = 0.f;
#pragma unroll
        for (int i = 0; i < 8; i++) t += redbuf[i];
        stat[0] = t;
    }
    __syncthreads();
    const float mu = stat[0] * (1.f / 768.f);

    float vs = 0.f;
#pragma unroll
    for (int i = 0; i < 3; i++) {
        float d = y[i] - mu;
        vs += d * d;
    }
#pragma unroll
    for (int o = 16; o > 0; o >>= 1) vs += __shfl_xor_sync(0xffffffffu, vs, o);
    if ((tid & 31) == 0) redbuf[tid >> 5] = vs;
    __syncthreads();
    if (tid == 0) {
        float t = 0.f;
#pragma unroll
        for (int i = 0; i < 8; i++) t += redbuf[i];
        stat[1] = t;
    }
    __syncthreads();
    const float rstd = rsqrtf(stat[1] * (1.f / 768.f) + 1e-5f);

    const bool valid = l < a_sizes[m];
    const int dst = a_starts[m] + l;
#pragma unroll
    for (int i = 0; i < 3; i++) {
        int col = tid + i * 256;
        float o = valid ? ((y[i] - mu) * rstd * gamma[col] + beta[col]) : 0.f;
        out[(size_t)dst * H + col] = o;
    }
}

// ---------------------------------------------------------------------------
extern "C" void kernel_launch(void* const* d_in, const int* in_sizes, int n_in,
                              void* d_out, int out_size) {
    const float* atom     = (const float*)d_in[0];
    const float* Wq       = (const float*)d_in[1];
    const float* bq       = (const float*)d_in[2];
    const float* Wk       = (const float*)d_in[3];
    const float* bk       = (const float*)d_in[4];
    const float* Wv       = (const float*)d_in[5];
    const float* bv       = (const float*)d_in[6];
    const float* Wo       = (const float*)d_in[7];
    const float* bo       = (const float*)d_in[8];
    const float* gamma    = (const float*)d_in[9];
    const float* beta     = (const float*)d_in[10];
    const int*   a_starts = (const int*)d_in[11];
    const int*   a_sizes  = (const int*)d_in[12];
    float* out = (float*)d_out;

    float *pX, *pQ, *pK, *pV;
    __nv_bfloat16 *pXhi, *pXlo, *pChi, *pClo, *pWhi, *pWlo;
    cudaGetSymbolAddress((void**)&pX, g_X);
    cudaGetSymbolAddress((void**)&pQ, g_Q);
    cudaGetSymbolAddress((void**)&pK, g_K);
    cudaGetSymbolAddress((void**)&pV, g_V);
    cudaGetSymbolAddress((void**)&pXhi, g_Xhi);
    cudaGetSymbolAddress((void**)&pXlo, g_Xlo);
    cudaGetSymbolAddress((void**)&pChi, g_Chi);
    cudaGetSymbolAddress((void**)&pClo, g_Clo);
    cudaGetSymbolAddress((void**)&pWhi, g_Whi);
    cudaGetSymbolAddress((void**)&pWlo, g_Wlo);
    const size_t WSZ = (size_t)H * H;

    cudaFuncSetAttribute(attn_tc_kernel, cudaFuncAttributeMaxDynamicSharedMemorySize,
                         ATT_SMEM);
    cudaFuncSetAttribute(gemm_bf16_kernel, cudaFuncAttributeMaxDynamicSharedMemorySize,
                         GEMM_SMEM);

    cudaMemsetAsync(d_out, 0, (size_t)out_size * sizeof(float), 0);

    build_x_kernel<<<(NROWS * H / 4) / 256, 256>>>(atom, a_starts, a_sizes);
    const int wblocks = (H * H / 4) / 256;   // 576
    cvt_w_kernel<<<wblocks, 256>>>(Wq, pWhi + 0 * WSZ, pWlo + 0 * WSZ);
    cvt_w_kernel<<<wblocks, 256>>>(Wk, pWhi + 1 * WSZ, pWlo + 1 * WSZ);
    cvt_w_kernel<<<wblocks, 256>>>(Wv, pWhi + 2 * WSZ, pWlo + 2 * WSZ);
    cvt_w_kernel<<<wblocks, 256>>>(Wo, pWhi + 3 * WSZ, pWlo + 3 * WSZ);

    dim3 ggrid(H / BN, NROWS / BM);    // (6, 256)
    gemm_bf16_kernel<<<ggrid, 256, GEMM_SMEM>>>(pXhi, pXlo, pWhi + 0 * WSZ,
                                                pWlo + 0 * WSZ, bq, pQ);
    gemm_bf16_kernel<<<ggrid, 256, GEMM_SMEM>>>(pXhi, pXlo, pWhi + 1 * WSZ,
                                                pWlo + 1 * WSZ, bk, pK);
    gemm_bf16_kernel<<<ggrid, 256, GEMM_SMEM>>>(pXhi, pXlo, pWhi + 2 * WSZ,
                                                pWlo + 2 * WSZ, bv, pV);

    attn_tc_kernel<<<dim3(NH, MOLS, 2), 256, ATT_SMEM>>>(a_sizes);

    gemm_bf16_kernel<<<ggrid, 256, GEMM_SMEM>>>(pChi, pClo, pWhi + 3 * WSZ,
                                                pWlo + 3 * WSZ, bo, pQ);

    ln_kernel<<<NROWS, 256>>>(gamma, beta, a_starts, a_sizes, out);
}

// round 6
// speedup vs baseline: 2.3909x; 1.0225x over previous
#include <cuda_runtime.h>
#include <cuda_bf16.h>
#include <cstdint>

#define MOLS 128
#define L 256
#define H 768
#define NH 12
#define HD 64
#define NROWS (MOLS * L)
#define NRH ((size_t)NROWS * H)
#define SCALE2 0.1803368801111204f   /* HD^-0.5 * log2(e) */

// ---- GEMM tiling ----
#define BM 128
#define BN 128
#define BK 32
#define KSTAGES (H / BK)     // 24
#define PIPE 3
#define ROWB 80              // padded smem row bytes (32 bf16 = 64B + 16B pad)
#define TILE_A (BM * ROWB)   // 10240
#define STAGE_BYTES (4 * TILE_A)           // Ahi, Alo, Bhi, Blo
#define GEMM_SMEM (PIPE * STAGE_BYTES)     // 122880

// ---- attention smem layout (bytes) ----
#define ATT_KHI 0
#define ATT_KLO 36864                      // 256 rows * 144
#define ATT_VHI 73728
#define ATT_VLO 107520                     // 64 rows * 528
#define ATT_SMEM 141312

// ---------------- scratch (device globals) ---------------------------------
__device__ __nv_bfloat16 g_Xhi[NRH];
__device__ __nv_bfloat16 g_Xlo[NRH];
__device__ __nv_bfloat16 g_PRJhi[3 * NRH];   // Q | K | V  (bf16 hi)
__device__ __nv_bfloat16 g_PRJlo[3 * NRH];   // Q | K | V  (bf16 lo)
__device__ __nv_bfloat16 g_Chi[NRH];
__device__ __nv_bfloat16 g_Clo[NRH];
__device__ __nv_bfloat16 g_Whi[4][(size_t)H * H];
__device__ __nv_bfloat16 g_Wlo[4][(size_t)H * H];
__device__ float g_O[NRH];                   // O-projection output (fp32)

// ---------------- helpers ---------------------------------------------------
__device__ __forceinline__ uint32_t smem_u32(const void* p) {
    uint32_t a;
    asm("{ .reg .u64 t; cvta.to.shared.u64 t, %1; cvt.u32.u64 %0, t; }"
        : "=r"(a) : "l"(p));
    return a;
}
__device__ __forceinline__ void cvt_hilo2(float a, float b, uint32_t& hi, uint32_t& lo) {
    __nv_bfloat162 h = __float22bfloat162_rn(make_float2(a, b));
    float2 hf = __bfloat1622float2(h);
    __nv_bfloat162 l = __float22bfloat162_rn(make_float2(a - hf.x, b - hf.y));
    hi = *(uint32_t*)&h;
    lo = *(uint32_t*)&l;
}
__device__ __forceinline__ float ex2(float x) {
    float y;
    asm("ex2.approx.ftz.f32 %0, %1;" : "=f"(y) : "f"(x));
    return y;
}
__device__ __forceinline__ void cp16(uint32_t s, const void* g) {
    asm volatile("cp.async.cg.shared.global [%0], [%1], 16;" :: "r"(s), "l"(g));
}
#define CP_COMMIT() asm volatile("cp.async.commit_group;" ::: "memory")
#define CP_WAIT1()  asm volatile("cp.async.wait_group 1;" ::: "memory")
#define LDM4(r0, r1, r2, r3, addr) \
    asm volatile("ldmatrix.sync.aligned.m8n8.x4.shared.b16 {%0,%1,%2,%3}, [%4];" \
                 : "=r"(r0), "=r"(r1), "=r"(r2), "=r"(r3) : "r"(addr))
__device__ __forceinline__ void mma_bf16(float d[4], const uint32_t a[4],
                                         uint32_t b0, uint32_t b1) {
    asm volatile(
        "mma.sync.aligned.m16n8k16.row.col.f32.bf16.bf16.f32 "
        "{%0,%1,%2,%3}, {%4,%5,%6,%7}, {%8,%9}, {%0,%1,%2,%3};\n"
        : "+f"(d[0]), "+f"(d[1]), "+f"(d[2]), "+f"(d[3])
        : "r"(a[0]), "r"(a[1]), "r"(a[2]), "r"(a[3]), "r"(b0), "r"(b1));
}

// ---------------- masked gather -> bf16 hi/lo only --------------------------
__global__ void build_x_kernel(const float* __restrict__ atom,
                               const int* __restrict__ a_starts,
                               const int* __restrict__ a_sizes) {
    int i = blockIdx.x * blockDim.x + threadIdx.x;     // float4 index
    const int W4 = H / 4;
    int row = i / W4;
    int c4  = (i - row * W4) * 4;
    int m = row / L;
    int l = row - m * L;
    float4 val = make_float4(0.f, 0.f, 0.f, 0.f);
    if (l < a_sizes[m]) {
        int src = a_starts[m] + l;
        val = *(const float4*)&atom[(size_t)src * H + c4];
    }
    size_t o = (size_t)row * H + c4;
    uint2 hi, lo;
    cvt_hilo2(val.x, val.y, hi.x, lo.x);
    cvt_hilo2(val.z, val.w, hi.y, lo.y);
    *(uint2*)&g_Xhi[o] = hi;
    *(uint2*)&g_Xlo[o] = lo;
}

// ---------------- all 4 weights fp32 -> bf16 hi/lo (Wq pre-scaled) ----------
__global__ void cvt_w_kernel(const float* __restrict__ W0, const float* __restrict__ W1,
                             const float* __restrict__ W2, const float* __restrict__ W3) {
    int i = blockIdx.x * blockDim.x + threadIdx.x;     // float4 idx over 4*H*H
    const int PW = H * H / 4;
    int slab = i / PW;
    int j = i - slab * PW;
    const float* W = (slab == 0) ? W0 : (slab == 1) ? W1 : (slab == 2) ? W2 : W3;
    float sc = (slab == 0) ? SCALE2 : 1.f;
    float4 v = ((const float4*)W)[j];
    uint2 h, l;
    cvt_hilo2(v.x * sc, v.y * sc, h.x, l.x);
    cvt_hilo2(v.z * sc, v.w * sc, h.y, l.y);
    ((uint2*)&g_Whi[0][0])[i] = h;
    ((uint2*)&g_Wlo[0][0])[i] = l;
}

// ---------------- bf16 compensated GEMM: D[n,o] = A·Bᵗ + bias ---------------
// SPLIT=true: QKV fused (grid.x = 18), writes bf16 hi/lo into g_PRJ slabs.
// SPLIT=false: O projection, writes fp32 into Cf with bias b0.
template <bool SPLIT>
__global__ __launch_bounds__(256, 1) void gemm_bf16_kernel(
    const __nv_bfloat16* __restrict__ Ahi, const __nv_bfloat16* __restrict__ Alo,
    const __nv_bfloat16* __restrict__ Bhi, const __nv_bfloat16* __restrict__ Blo,
    const float* __restrict__ b0, const float* __restrict__ b1,
    const float* __restrict__ b2, float* __restrict__ Cf,
    __nv_bfloat16* __restrict__ Dhi, __nv_bfloat16* __restrict__ Dlo) {
    extern __shared__ char sm[];
    const uint32_t smb = smem_u32(sm);
    const int tid = threadIdx.x;
    const int lane = tid & 31;
    const int wid = tid >> 5;
    const int wm = wid >> 2;            // 0..1
    const int wn = wid & 3;             // 0..3
    const int bm = blockIdx.y * BM;
    const int bn = blockIdx.x * BN;

    float acc[4][4][4];
#pragma unroll
    for (int i = 0; i < 4; i++)
#pragma unroll
        for (int j = 0; j < 4; j++)
#pragma unroll
            for (int t = 0; t < 4; t++) acc[i][j][t] = 0.f;

    const int c0 = tid * 2;
    const int r0 = c0 >> 2, kc0 = (c0 & 3);
    const int r1 = (c0 + 1) >> 2, kc1 = ((c0 + 1) & 3);

    auto load_stage = [&](int buf, int k0) {
        uint32_t sb = smb + buf * STAGE_BYTES;
        size_t ga0 = (size_t)(bm + r0) * H + k0 + kc0 * 8;
        size_t ga1 = (size_t)(bm + r1) * H + k0 + kc1 * 8;
        size_t gb0 = (size_t)(bn + r0) * H + k0 + kc0 * 8;
        size_t gb1 = (size_t)(bn + r1) * H + k0 + kc1 * 8;
        uint32_t s0 = r0 * ROWB + kc0 * 16;
        uint32_t s1 = r1 * ROWB + kc1 * 16;
        cp16(sb + s0, Ahi + ga0);
        cp16(sb + s1, Ahi + ga1);
        cp16(sb + TILE_A + s0, Alo + ga0);
        cp16(sb + TILE_A + s1, Alo + ga1);
        cp16(sb + 2 * TILE_A + s0, Bhi + gb0);
        cp16(sb + 2 * TILE_A + s1, Bhi + gb1);
        cp16(sb + 3 * TILE_A + s0, Blo + gb0);
        cp16(sb + 3 * TILE_A + s1, Blo + gb1);
    };

    load_stage(0, 0);
    CP_COMMIT();
    load_stage(1, BK);
    CP_COMMIT();

    const int trow = lane & 15;
    const int tkb = (lane >> 4) * 16;

#pragma unroll 1
    for (int ks = 0; ks < KSTAGES; ks++) {
        CP_WAIT1();
        __syncthreads();
        int nxt = ks + 2;
        if (nxt < KSTAGES) load_stage(nxt % PIPE, nxt * BK);
        CP_COMMIT();

        const uint32_t sA = smb + (ks % PIPE) * STAGE_BYTES;
        const uint32_t sB = sA + 2 * TILE_A;
#pragma unroll
        for (int kh = 0; kh < 2; kh++) {
            const uint32_t koff = kh * 32 + tkb;
            uint32_t ah[4][4], al[4][4], bh[2][4], bl[2][4];
#pragma unroll
            for (int mt = 0; mt < 4; mt++) {
                uint32_t a = sA + (wm * 64 + mt * 16 + trow) * ROWB + koff;
                LDM4(ah[mt][0], ah[mt][1], ah[mt][2], ah[mt][3], a);
                LDM4(al[mt][0], al[mt][1], al[mt][2], al[mt][3], a + TILE_A);
            }
#pragma unroll
            for (int g = 0; g < 2; g++) {
                uint32_t b = sB + (wn * 32 + g * 16 + trow) * ROWB + koff;
                LDM4(bh[g][0], bh[g][1], bh[g][2], bh[g][3], b);
                LDM4(bl[g][0], bl[g][1], bl[g][2], bl[g][3], b + TILE_A);
            }
#pragma unroll
            for (int mt = 0; mt < 4; mt++)
#pragma unroll
                for (int nt = 0; nt < 4; nt++) {
                    const int g = nt >> 1, s = nt & 1;
                    mma_bf16(acc[mt][nt], ah[mt], bh[g][s], bh[g][s + 2]);
                    mma_bf16(acc[mt][nt], ah[mt], bl[g][s], bl[g][s + 2]);
                    mma_bf16(acc[mt][nt], al[mt], bh[g][s], bh[g][s + 2]);
                }
        }
    }

    if (SPLIT) {
        // QKV: select section, write bf16 hi/lo (Q pre-scaled via folded Wq/bias)
        const int sect = blockIdx.x / 6;                 // 0=Q 1=K 2=V
        const int coff = bn - sect * 768;
        const float* bias = (sect == 0) ? b0 : (sect == 1) ? b1 : b2;
        const float bscale = (sect == 0) ? SCALE2 : 1.f;
        __nv_bfloat16* dhi = Dhi + (size_t)sect * NRH;
        __nv_bfloat16* dlo = Dlo + (size_t)sect * NRH;
#pragma unroll
        for (int mt = 0; mt < 4; mt++) {
            int row = bm + wm * 64 + mt * 16 + (lane >> 2);
#pragma unroll
            for (int nt = 0; nt < 4; nt++) {
                int cl = coff + wn * 32 + nt * 8 + (lane & 3) * 2;
                float bb0 = bias[cl] * bscale, bb1 = bias[cl + 1] * bscale;
                uint32_t hi, lo;
                size_t o = (size_t)row * H + cl;
                cvt_hilo2(acc[mt][nt][0] + bb0, acc[mt][nt][1] + bb1, hi, lo);
                *(uint32_t*)&dhi[o] = hi;
                *(uint32_t*)&dlo[o] = lo;
                cvt_hilo2(acc[mt][nt][2] + bb0, acc[mt][nt][3] + bb1, hi, lo);
                *(uint32_t*)&dhi[o + 8 * H] = hi;
                *(uint32_t*)&dlo[o + 8 * H] = lo;
            }
        }
    } else {
#pragma unroll
        for (int mt = 0; mt < 4; mt++) {
            int row = bm + wm * 64 + mt * 16 + (lane >> 2);
#pragma unroll
            for (int nt = 0; nt < 4; nt++) {
                int col = bn + wn * 32 + nt * 8 + (lane & 3) * 2;
                float2 bb = *(const float2*)&b0[col];
                float* p = Cf + (size_t)row * H + col;
                *(float2*)p = make_float2(acc[mt][nt][0] + bb.x, acc[mt][nt][1] + bb.y);
                *(float2*)(p + 8 * H) =
                    make_float2(acc[mt][nt][2] + bb.x, acc[mt][nt][3] + bb.y);
            }
        }
    }
}

// ---------------- tensor-core flash attention -------------------------------
// Q/K/V already bf16 hi/lo in g_PRJ (Q pre-scaled, log2 domain).
__global__ __launch_bounds__(256, 1) void attn_tc_kernel(const int* __restrict__ a_sizes) {
    extern __shared__ char sm[];
    const uint32_t smb = smem_u32(sm);
    const int h = blockIdx.x, m = blockIdx.y;
    const int tid = threadIdx.x;
    const int lane = tid & 31;
    const int wid = tid >> 5;
    const int size = a_sizes[m];

    const __nv_bfloat16* Qhi = g_PRJhi;
    const __nv_bfloat16* Qlo = g_PRJlo;
    const __nv_bfloat16* Khi = g_PRJhi + NRH;
    const __nv_bfloat16* Klo = g_PRJlo + NRH;
    const __nv_bfloat16* Vhi = g_PRJhi + 2 * NRH;
    const __nv_bfloat16* Vlo = g_PRJlo + 2 * NRH;

    // ---- stage K (row-major, pitch 144B): pure 16B copies ----
#pragma unroll
    for (int it = 0; it < 8; it++) {
        int i = tid + it * 256;
        int row = i >> 3, ch = (i & 7) * 8;
        size_t src = (size_t)(m * L + row) * H + h * HD + ch;
        *(uint4*)(sm + ATT_KHI + row * 144 + ch * 2) = *(const uint4*)&Khi[src];
        *(uint4*)(sm + ATT_KLO + row * 144 + ch * 2) = *(const uint4*)&Klo[src];
    }
    // ---- stage V^T (pitch 528B): transpose via 2B reads ----
#pragma unroll
    for (int it = 0; it < 32; it++) {
        int p = tid + it * 256;
        int d = p & 63, j = (p >> 6) * 2;
        size_t s0 = (size_t)(m * L + j) * H + h * HD + d;
        uint32_t h0 = *(const unsigned short*)&Vhi[s0];
        uint32_t h1 = *(const unsigned short*)&Vhi[s0 + H];
        uint32_t l0v = *(const unsigned short*)&Vlo[s0];
        uint32_t l1v = *(const unsigned short*)&Vlo[s0 + H];
        *(uint32_t*)(sm + ATT_VHI + d * 528 + j * 2) = h0 | (h1 << 16);
        *(uint32_t*)(sm + ATT_VLO + d * 528 + j * 2) = l0v | (l1v << 16);
    }
    __syncthreads();

    const int tq2 = (lane & 3) * 2;
    const int l15 = lane & 15;
    const int lhk = (lane >> 4) * 16;
    const int row0 = blockIdx.z * 128 + wid * 16 + (lane >> 2);

    // Q fragments straight from gmem (already scaled + split)
    uint32_t qhi[4][4], qlo[4][4];
    {
        const size_t qb = (size_t)(m * L + row0) * H + h * HD;
#pragma unroll
        for (int ks = 0; ks < 4; ks++) {
            int k = ks * 16 + tq2;
            qhi[ks][0] = *(const uint32_t*)&Qhi[qb + k];
            qhi[ks][1] = *(const uint32_t*)&Qhi[qb + 8 * H + k];
            qhi[ks][2] = *(const uint32_t*)&Qhi[qb + k + 8];
            qhi[ks][3] = *(const uint32_t*)&Qhi[qb + 8 * H + k + 8];
            qlo[ks][0] = *(const uint32_t*)&Qlo[qb + k];
            qlo[ks][1] = *(const uint32_t*)&Qlo[qb + 8 * H + k];
            qlo[ks][2] = *(const uint32_t*)&Qlo[qb + k + 8];
            qlo[ks][3] = *(const uint32_t*)&Qlo[qb + 8 * H + k + 8];
        }
    }

    float O[8][4];
#pragma unroll
    for (int i = 0; i < 8; i++)
#pragma unroll
        for (int j = 0; j < 4; j++) O[i][j] = 0.f;
    float m0 = -1e30f, m1 = -1e30f, l0 = 0.f, l1 = 0.f;

    const int nch = min(4, (size + 63) >> 6);
#pragma unroll 1
    for (int c = 0; c < nch; c++) {
        const int j0 = c * 64;
        float S[8][4];
#pragma unroll
        for (int i = 0; i < 8; i++)
#pragma unroll
            for (int j = 0; j < 4; j++) S[i][j] = 0.f;

#pragma unroll
        for (int np = 0; np < 4; np++) {
            uint32_t kra = smb + ATT_KHI + (j0 + np * 16 + l15) * 144 + lhk;
#pragma unroll
            for (int ks = 0; ks < 4; ks++) {
                uint32_t kh0, kh1, kh2, kh3, kl0, kl1, kl2, kl3;
                LDM4(kh0, kh1, kh2, kh3, kra + ks * 32);
                LDM4(kl0, kl1, kl2, kl3, kra + ks * 32 + (ATT_KLO - ATT_KHI));
                mma_bf16(S[2 * np], qhi[ks], kh0, kh2);
                mma_bf16(S[2 * np], qlo[ks], kh0, kh2);
                mma_bf16(S[2 * np], qhi[ks], kl0, kl2);
                mma_bf16(S[2 * np + 1], qhi[ks], kh1, kh3);
                mma_bf16(S[2 * np + 1], qlo[ks], kh1, kh3);
                mma_bf16(S[2 * np + 1], qhi[ks], kl1, kl3);
            }
        }

        if (j0 + 64 > size) {
#pragma unroll
            for (int nt = 0; nt < 8; nt++) {
                int col = j0 + nt * 8 + tq2;
                if (col >= size)     { S[nt][0] = -1e30f; S[nt][2] = -1e30f; }
                if (col + 1 >= size) { S[nt][1] = -1e30f; S[nt][3] = -1e30f; }
            }
        }

        float mx0 = -1e30f, mx1 = -1e30f;
#pragma unroll
        for (int nt = 0; nt < 8; nt++) {
            mx0 = fmaxf(mx0, fmaxf(S[nt][0], S[nt][1]));
            mx1 = fmaxf(mx1, fmaxf(S[nt][2], S[nt][3]));
        }
        mx0 = fmaxf(mx0, __shfl_xor_sync(0xffffffffu, mx0, 1));
        mx0 = fmaxf(mx0, __shfl_xor_sync(0xffffffffu, mx0, 2));
        mx1 = fmaxf(mx1, __shfl_xor_sync(0xffffffffu, mx1, 1));
        mx1 = fmaxf(mx1, __shfl_xor_sync(0xffffffffu, mx1, 2));
        float nm0 = fmaxf(m0, mx0), nm1 = fmaxf(m1, mx1);
        float f0 = ex2(m0 - nm0), f1 = ex2(m1 - nm1);
        float rs0 = 0.f, rs1 = 0.f;
#pragma unroll
        for (int nt = 0; nt < 8; nt++) {
            S[nt][0] = ex2(S[nt][0] - nm0); rs0 += S[nt][0];
            S[nt][1] = ex2(S[nt][1] - nm0); rs0 += S[nt][1];
            S[nt][2] = ex2(S[nt][2] - nm1); rs1 += S[nt][2];
            S[nt][3] = ex2(S[nt][3] - nm1); rs1 += S[nt][3];
        }
        rs0 += __shfl_xor_sync(0xffffffffu, rs0, 1);
        rs0 += __shfl_xor_sync(0xffffffffu, rs0, 2);
        rs1 += __shfl_xor_sync(0xffffffffu, rs1, 1);
        rs1 += __shfl_xor_sync(0xffffffffu, rs1, 2);
        l0 = l0 * f0 + rs0;
        l1 = l1 * f1 + rs1;
        m0 = nm0; m1 = nm1;
#pragma unroll
        for (int dt = 0; dt < 8; dt++) {
            O[dt][0] *= f0; O[dt][1] *= f0;
            O[dt][2] *= f1; O[dt][3] *= f1;
        }

        uint32_t phi[4][4], plo[4][4];
#pragma unroll
        for (int ks = 0; ks < 4; ks++) {
            cvt_hilo2(S[2 * ks][0], S[2 * ks][1], phi[ks][0], plo[ks][0]);
            cvt_hilo2(S[2 * ks][2], S[2 * ks][3], phi[ks][1], plo[ks][1]);
            cvt_hilo2(S[2 * ks + 1][0], S[2 * ks + 1][1], phi[ks][2], plo[ks][2]);
            cvt_hilo2(S[2 * ks + 1][2], S[2 * ks + 1][3], phi[ks][3], plo[ks][3]);
        }

#pragma unroll
        for (int dp = 0; dp < 4; dp++) {
            uint32_t vra = smb + ATT_VHI + (dp * 16 + l15) * 528 + j0 * 2 + lhk;
#pragma unroll
            for (int ks = 0; ks < 4; ks++) {
                uint32_t vh0, vh1, vh2, vh3, vl0, vl1, vl2, vl3;
                LDM4(vh0, vh1, vh2, vh3, vra + ks * 32);
                LDM4(vl0, vl1, vl2, vl3, vra + ks * 32 + (ATT_VLO - ATT_VHI));
                mma_bf16(O[2 * dp], phi[ks], vh0, vh2);
                mma_bf16(O[2 * dp], plo[ks], vh0, vh2);
                mma_bf16(O[2 * dp], phi[ks], vl0, vl2);
                mma_bf16(O[2 * dp + 1], phi[ks], vh1, vh3);
                mma_bf16(O[2 * dp + 1], plo[ks], vh1, vh3);
                mma_bf16(O[2 * dp + 1], phi[ks], vl1, vl3);
            }
        }
    }

    const float i0 = 1.f / l0, i1 = 1.f / l1;
    const size_t ob = (size_t)(m * L + row0) * H + h * HD + tq2;
#pragma unroll
    for (int dt = 0; dt < 8; dt++) {
        uint32_t hi, lo;
        cvt_hilo2(O[dt][0] * i0, O[dt][1] * i0, hi, lo);
        *(uint32_t*)&g_Chi[ob + dt * 8] = hi;
        *(uint32_t*)&g_Clo[ob + dt * 8] = lo;
        cvt_hilo2(O[dt][2] * i1, O[dt][3] * i1, hi, lo);
        *(uint32_t*)&g_Chi[ob + 8 * H + dt * 8] = hi;
        *(uint32_t*)&g_Clo[ob + 8 * H + dt * 8] = lo;
    }
}

// -------- residual + LayerNorm + mask + scatter (covers ALL rows) ----------
__global__ __launch_bounds__(256) void ln_kernel(
    const float* __restrict__ atom,
    const float* __restrict__ gamma, const float* __restrict__ beta,
    const int* __restrict__ a_starts, const int* __restrict__ a_sizes,
    float* __restrict__ out) {
    const int row = blockIdx.x;
    const int m = row / L;
    const int l = row - m * L;
    const int tid = threadIdx.x;

    __shared__ float redbuf[8];
    __shared__ float stat[2];

    const bool valid = l < a_sizes[m];
    const int dst = a_starts[m] + l;

    float y[3];
    float s = 0.f;
#pragma unroll
    for (int i = 0; i < 3; i++) {
        int col = tid + i * 256;
        float xv = valid ? atom[(size_t)dst * H + col] : 0.f;
        float v = g_O[(size_t)row * H + col] + xv;
        y[i] = v;
        s += v;
    }
#pragma unroll
    for (int o = 16; o > 0; o >>= 1) s += __shfl_xor_sync(0xffffffffu, s, o);
    if ((tid & 31) == 0) redbuf[tid >> 5] = s;
    __syncthreads();
    if (tid == 0) {
        float t = 0.f;
#pragma unroll
        for (int i = 0; i < 8; i++) t += redbuf[i];
        stat[0] = t;
    }
    __syncthreads();
    const float mu = stat[0] * (1.f / 768.f);

    float vs = 0.f;
#pragma unroll
    for (int i = 0; i < 3; i++) {
        float d = y[i] - mu;
        vs += d * d;
    }
#pragma unroll
    for (int o = 16; o > 0; o >>= 1) vs += __shfl_xor_sync(0xffffffffu, vs, o);
    if ((tid & 31) == 0) redbuf[tid >> 5] = vs;
    __syncthreads();
    if (tid == 0) {
        float t = 0.f;
#pragma unroll
        for (int i = 0; i < 8; i++) t += redbuf[i];
        stat[1] = t;
    }
    __syncthreads();
    const float rstd = rsqrtf(stat[1] * (1.f / 768.f) + 1e-5f);

#pragma unroll
    for (int i = 0; i < 3; i++) {
        int col = tid + i * 256;
        float o = valid ? ((y[i] - mu) * rstd * gamma[col] + beta[col]) : 0.f;
        out[(size_t)dst * H + col] = o;
    }
}

// ---------------------------------------------------------------------------
extern "C" void kernel_launch(void* const* d_in, const int* in_sizes, int n_in,
                              void* d_out, int out_size) {
    const float* atom     = (const float*)d_in[0];
    const float* Wq       = (const float*)d_in[1];
    const float* bq       = (const float*)d_in[2];
    const float* Wk       = (const float*)d_in[3];
    const float* bk       = (const float*)d_in[4];
    const float* Wv       = (const float*)d_in[5];
    const float* bv       = (const float*)d_in[6];
    const float* Wo       = (const float*)d_in[7];
    const float* bo       = (const float*)d_in[8];
    const float* gamma    = (const float*)d_in[9];
    const float* beta     = (const float*)d_in[10];
    const int*   a_starts = (const int*)d_in[11];
    const int*   a_sizes  = (const int*)d_in[12];
    float* out = (float*)d_out;

    __nv_bfloat16 *pXhi, *pXlo, *pPhi, *pPlo, *pChi, *pClo, *pWhi, *pWlo;
    float* pO;
    cudaGetSymbolAddress((void**)&pXhi, g_Xhi);
    cudaGetSymbolAddress((void**)&pXlo, g_Xlo);
    cudaGetSymbolAddress((void**)&pPhi, g_PRJhi);
    cudaGetSymbolAddress((void**)&pPlo, g_PRJlo);
    cudaGetSymbolAddress((void**)&pChi, g_Chi);
    cudaGetSymbolAddress((void**)&pClo, g_Clo);
    cudaGetSymbolAddress((void**)&pWhi, g_Whi);
    cudaGetSymbolAddress((void**)&pWlo, g_Wlo);
    cudaGetSymbolAddress((void**)&pO, g_O);
    const size_t WSZ = (size_t)H * H;

    cudaFuncSetAttribute(attn_tc_kernel, cudaFuncAttributeMaxDynamicSharedMemorySize,
                         ATT_SMEM);
    cudaFuncSetAttribute(gemm_bf16_kernel<true>,
                         cudaFuncAttributeMaxDynamicSharedMemorySize, GEMM_SMEM);
    cudaFuncSetAttribute(gemm_bf16_kernel<false>,
                         cudaFuncAttributeMaxDynamicSharedMemorySize, GEMM_SMEM);

    build_x_kernel<<<(NROWS * H / 4) / 256, 256>>>(atom, a_starts, a_sizes);
    cvt_w_kernel<<<(4 * H * H / 4) / 256, 256>>>(Wq, Wk, Wv, Wo);

    // fused QKV: N = 2304
    dim3 qkvgrid(2304 / BN, NROWS / BM);    // (18, 256)
    gemm_bf16_kernel<true><<<qkvgrid, 256, GEMM_SMEM>>>(
        pXhi, pXlo, pWhi, pWlo, bq, bk, bv, nullptr, pPhi, pPlo);

    attn_tc_kernel<<<dim3(NH, MOLS, 2), 256, ATT_SMEM>>>(a_sizes);

    dim3 ogrid(H / BN, NROWS / BM);         // (6, 256)
    gemm_bf16_kernel<false><<<ogrid, 256, GEMM_SMEM>>>(
        pChi, pClo, pWhi + 3 * WSZ, pWlo + 3 * WSZ, bo, nullptr, nullptr, pO,
        nullptr, nullptr);

    ln_kernel<<<NROWS, 256>>>(atom, gamma, beta, a_starts, a_sizes, out);
}